// round 7
// baseline (speedup 1.0000x reference)
#include <cuda_runtime.h>
#include <cuda_bf16.h>
#include <math.h>
#include <stdint.h>

#define BB 64
#define TT 1024
#define INF 512
#define HH 768
#define GG 3072          // 4*H
#define MM (BB*TT)       // 65536
#define OUTD 100
#define BBHH (BB*HH)

// recurrence config
#define NCTA 128
#define JC 6             // h columns per CTA
#define NC 24            // gate rows per CTA (4*JC)
#define NCHR 12          // 768/64 k-chunks
#define WROWB 1552       // W smem row pitch bytes (768*2 + 16)
#define HROWB 144        // h tile row pitch bytes (64*2 + 16)
#define HTILE (64*HROWB) // 9216
#define WTILE (NC*WROWB) // 37248

// GEMM config
#define GAT (128*HROWB)  // 18432 bytes: one 128x64 bf16 tile
#define GSMEM (6*GAT)    // 3 stages x (A,B) = 110592
#define RSMEM (2*WTILE + 6*HTILE + 64*28*4 + 64*24*4)  // 143104

// ---------------- scratch (device globals; no allocation allowed) ----------------
__device__ float g_pre[(size_t)MM * GG];
__device__ float g_x1[(size_t)MM * HH];
__device__ float g_x2[(size_t)MM * HH];
__device__ float g_x3[(size_t)MM * HH];
__device__ float g_proj[(size_t)MM * 128];
__device__ float g_c[BBHH];
__device__ __nv_bfloat16 g_hb[2][2][BBHH];   // [parity][hi/lo]
__device__ unsigned g_flags[NCTA];           // per-CTA barrier flags (monotonic)
// bf16 split buffers
__device__ __nv_bfloat16 g_ah[(size_t)MM * HH];
__device__ __nv_bfloat16 g_al[(size_t)MM * HH];
__device__ __nv_bfloat16 g_bh[(size_t)GG * HH];
__device__ __nv_bfloat16 g_bl[(size_t)GG * HH];
__device__ __nv_bfloat16 g_ph[128 * HH];
__device__ __nv_bfloat16 g_pl[128 * HH];

// ---------------- ptx helpers (base sm_103 ISA only) ----------------
__device__ __forceinline__ void cpasync16(uint32_t saddr, const void* g) {
    asm volatile("cp.async.cg.shared.global [%0], [%1], 16;\n" :: "r"(saddr), "l"(g));
}
__device__ __forceinline__ void cpasync8(uint32_t saddr, const void* g) {
    asm volatile("cp.async.ca.shared.global [%0], [%1], 8;\n" :: "r"(saddr), "l"(g));
}
__device__ __forceinline__ void cpcommit() { asm volatile("cp.async.commit_group;\n"); }
template<int N> __device__ __forceinline__ void cpwait() {
    asm volatile("cp.async.wait_group %0;\n" :: "n"(N));
}
__device__ __forceinline__ uint32_t smem_u32(const void* p) {
    return (uint32_t)__cvta_generic_to_shared(p);
}
__device__ __forceinline__ void ldsm4(uint32_t addr, uint32_t* r) {
    asm volatile("ldmatrix.sync.aligned.m8n8.x4.shared.b16 {%0,%1,%2,%3}, [%4];"
                 : "=r"(r[0]), "=r"(r[1]), "=r"(r[2]), "=r"(r[3]) : "r"(addr));
}
__device__ __forceinline__ void ldsm2(uint32_t addr, uint32_t* r) {
    asm volatile("ldmatrix.sync.aligned.m8n8.x2.shared.b16 {%0,%1}, [%2];"
                 : "=r"(r[0]), "=r"(r[1]) : "r"(addr));
}
__device__ __forceinline__ void mma_bf16(float* d, const uint32_t* a, uint32_t b0, uint32_t b1) {
    asm volatile(
        "mma.sync.aligned.m16n8k16.row.col.f32.bf16.bf16.f32 "
        "{%0,%1,%2,%3}, {%4,%5,%6,%7}, {%8,%9}, {%0,%1,%2,%3};"
        : "+f"(d[0]), "+f"(d[1]), "+f"(d[2]), "+f"(d[3])
        : "r"(a[0]), "r"(a[1]), "r"(a[2]), "r"(a[3]), "r"(b0), "r"(b1));
}

// ---------------- bf16 split conversions ----------------
__global__ void split_bf16(const float* __restrict__ src,
                           __nv_bfloat16* __restrict__ hi,
                           __nv_bfloat16* __restrict__ lo, size_t n4)
{
    size_t i = (size_t)blockIdx.x * blockDim.x + threadIdx.x;
    size_t stride = (size_t)gridDim.x * blockDim.x;
    for (; i < n4; i += stride) {
        float4 v = ((const float4*)src)[i];
        __nv_bfloat16 h0 = __float2bfloat16(v.x);
        __nv_bfloat16 h1 = __float2bfloat16(v.y);
        __nv_bfloat16 h2 = __float2bfloat16(v.z);
        __nv_bfloat16 h3 = __float2bfloat16(v.w);
        __nv_bfloat162 hp0; hp0.x = h0; hp0.y = h1;
        __nv_bfloat162 hp1; hp1.x = h2; hp1.y = h3;
        __nv_bfloat162 lp0;
        lp0.x = __float2bfloat16(v.x - __bfloat162float(h0));
        lp0.y = __float2bfloat16(v.y - __bfloat162float(h1));
        __nv_bfloat162 lp1;
        lp1.x = __float2bfloat16(v.z - __bfloat162float(h2));
        lp1.y = __float2bfloat16(v.w - __bfloat162float(h3));
        ((__nv_bfloat162*)hi)[2*i]   = hp0;
        ((__nv_bfloat162*)hi)[2*i+1] = hp1;
        ((__nv_bfloat162*)lo)[2*i]   = lp0;
        ((__nv_bfloat162*)lo)[2*i+1] = lp1;
    }
}

__global__ void pad_wp_split(__nv_bfloat16* __restrict__ ph,
                             __nv_bfloat16* __restrict__ pl,
                             const float* __restrict__ Wp)
{
    int i = blockIdx.x * blockDim.x + threadIdx.x;
    int stride = gridDim.x * blockDim.x;
    for (; i < 128 * HH; i += stride) {
        int o = i / HH, k = i % HH;
        float v = (o < OUTD) ? Wp[o * HH + k] : 0.f;
        __nv_bfloat16 h = __float2bfloat16(v);
        ph[i] = h;
        pl[i] = __float2bfloat16(v - __bfloat162float(h));
    }
}

// ---------------- bf16x3 GEMM via mma.sync (ring-3 pipeline) ----------------
__device__ __forceinline__ void gemm_issue(uint32_t sb, int stage,
                                           const __nv_bfloat16* Ag,
                                           const __nv_bfloat16* Bg,
                                           int K, int tid)
{
    uint32_t dA = sb + stage * 2 * GAT;
    uint32_t dB = dA + GAT;
#pragma unroll
    for (int it = 0; it < 4; it++) {
        int idx = it * 256 + tid;
        int row = idx >> 3, seg = idx & 7;
        cpasync16(dA + row * HROWB + seg * 16, Ag + (size_t)row * K + seg * 8);
    }
#pragma unroll
    for (int it = 0; it < 4; it++) {
        int idx = it * 256 + tid;
        int row = idx >> 3, seg = idx & 7;
        cpasync16(dB + row * HROWB + seg * 16, Bg + (size_t)row * K + seg * 8);
    }
    cpcommit();
}

__global__ __launch_bounds__(256)
void gemm_mma3(const __nv_bfloat16* __restrict__ Ah, const __nv_bfloat16* __restrict__ Al,
               const __nv_bfloat16* __restrict__ Bh, const __nv_bfloat16* __restrict__ Bl,
               const float* __restrict__ bias, float* __restrict__ C,
               int K, int Ntot)
{
    extern __shared__ __align__(128) char gsm[];
    uint32_t sb = smem_u32(gsm);

    int tid = threadIdx.x;
    int lane = tid & 31;
    int wid = tid >> 5;
    int wm = wid & 3;
    int wn = wid >> 2;
    int m0 = blockIdx.y * 128;
    int n0 = blockIdx.x * 128;

    const __nv_bfloat16* As_[3] = { Ah, Ah, Al };
    const __nv_bfloat16* Bs_[3] = { Bh, Bl, Bh };
    const int cps = K >> 6;
    const int nch = 3 * cps;

    float acc[2][8][4];
#pragma unroll
    for (int mt = 0; mt < 2; mt++)
#pragma unroll
        for (int f = 0; f < 8; f++)
#pragma unroll
            for (int r = 0; r < 4; r++) acc[mt][f][r] = 0.f;

    int aRow = (lane & 15);
    int aHalf = (lane >> 4) * 16;
    int gB = lane >> 3;
    int bHalf = (gB & 1) * 16;

    // preamble: issue chunk 0 and 1
    {
        gemm_issue(sb, 0, As_[0] + (size_t)m0 * K, Bs_[0] + (size_t)n0 * K, K, tid);
        int s1 = 1 / cps, ck1 = (1 - s1 * cps) * 64;
        gemm_issue(sb, 1, As_[s1] + (size_t)m0 * K + ck1, Bs_[s1] + (size_t)n0 * K + ck1, K, tid);
    }

    for (int c = 0; c < nch; c++) {
        int stage = c % 3;
        if (c + 2 < nch) {
            int cn = c + 2;
            int s = cn / cps, ck = (cn - s * cps) * 64;
            gemm_issue(sb, (c + 2) % 3, As_[s] + (size_t)m0 * K + ck,
                       Bs_[s] + (size_t)n0 * K + ck, K, tid);
            cpwait<2>();
        } else if (c + 1 < nch) {
            cpwait<1>();
        } else {
            cpwait<0>();
        }
        __syncthreads();
        uint32_t A = sb + stage * 2 * GAT;
        uint32_t B = A + GAT;
#pragma unroll
        for (int kk = 0; kk < 4; kk++) {
            uint32_t a[2][4];
#pragma unroll
            for (int mt = 0; mt < 2; mt++)
                ldsm4(A + (wm*32 + mt*16 + aRow) * HROWB + aHalf + kk*32, a[mt]);
            uint32_t bfr[8][2];
#pragma unroll
            for (int fp = 0; fp < 4; fp++) {
                int fi = fp * 2 + (gB >> 1);
                uint32_t r4[4];
                ldsm4(B + (wn*64 + fi*8 + (lane & 7)) * HROWB + bHalf + kk*32, r4);
                bfr[fp*2][0]   = r4[0]; bfr[fp*2][1]   = r4[1];
                bfr[fp*2+1][0] = r4[2]; bfr[fp*2+1][1] = r4[3];
            }
#pragma unroll
            for (int mt = 0; mt < 2; mt++)
#pragma unroll
                for (int f = 0; f < 8; f++)
                    mma_bf16(acc[mt][f], a[mt], bfr[f][0], bfr[f][1]);
        }
        __syncthreads();
    }

    int g4 = lane >> 2, tig = lane & 3;
#pragma unroll
    for (int mt = 0; mt < 2; mt++) {
#pragma unroll
        for (int f = 0; f < 8; f++) {
            int r0 = m0 + wm*32 + mt*16 + g4;
            int c0 = n0 + wn*64 + f*8 + tig*2;
            float b0 = bias ? bias[c0] : 0.f;
            float b1 = bias ? bias[c0+1] : 0.f;
            float2 v0; v0.x = acc[mt][f][0] + b0; v0.y = acc[mt][f][1] + b1;
            float2 v1; v1.x = acc[mt][f][2] + b0; v1.y = acc[mt][f][3] + b1;
            *(float2*)&C[(size_t)r0 * Ntot + c0] = v0;
            *(float2*)&C[(size_t)(r0 + 8) * Ntot + c0] = v1;
        }
    }
}

// ---------------- persistent LSTM with mma recurrence ----------------
__device__ __forceinline__ void rec_issue(uint32_t hbA, int slot,
                                          const __nv_bfloat16* hhi,
                                          const __nv_bfloat16* hlo,
                                          int k0, int tid)
{
    uint32_t dH = hbA + slot * 2 * HTILE;
    uint32_t dL = dH + HTILE;
#pragma unroll
    for (int it = 0; it < 4; it++) {
        int idx = it * 128 + tid;
        int row = idx >> 3, seg = idx & 7;
        cpasync16(dH + row * HROWB + seg * 16, hhi + (size_t)row * HH + k0 + seg * 8);
        cpasync16(dL + row * HROWB + seg * 16, hlo + (size_t)row * HH + k0 + seg * 8);
    }
}

// prefetch pre[.,t,.] slice for this CTA into SMEM (24 floats per batch row)
__device__ __forceinline__ void pre_issue(uint32_t psm, const float* pre,
                                          int t, int j0, int tid)
{
#pragma unroll
    for (int r = 0; r < 6; r++) {
        int i = r * 128 + tid;         // 0..767
        int b = i / 12;
        int rem = i - b * 12;
        int g = rem / 3;
        int part = rem - g * 3;
        cpasync8(psm + (uint32_t)(b * 24 + g * 6 + part * 2) * 4,
                 pre + ((size_t)b * TT + t) * GG + g * HH + j0 + part * 2);
    }
}

__global__ __launch_bounds__(128, 1)
void lstm_persist(const float* __restrict__ pre, const float* __restrict__ Whh,
                  __nv_bfloat16* __restrict__ hb, float* __restrict__ cst,
                  float* __restrict__ y, const float* __restrict__ res)
{
    extern __shared__ __align__(128) char rsm[];
    char* Whi = rsm;
    char* Wlo = rsm + WTILE;
    char* Hb  = rsm + 2 * WTILE;                       // ring of 3 x (hi+lo)
    float* Csm = (float*)(rsm + 2 * WTILE + 6 * HTILE);
    float* Psm = (float*)(rsm + 2 * WTILE + 6 * HTILE + 64 * 28 * 4);
    __shared__ unsigned s_base;

    int tid = threadIdx.x;
    int lane = tid & 31;
    int w = tid >> 5;
    int j0 = blockIdx.x * JC;

    if (tid == 0) s_base = *(volatile unsigned*)&g_flags[blockIdx.x];

    // cache Whh slice as bf16 hi/lo. SMEM row r = gate r/JC, col j0 + r%JC.
    for (int i = tid; i < NC * HH; i += 128) {
        int r = i / HH, k = i - r * HH;
        int g = r / JC, jj = r - g * JC;
        float v = Whh[(size_t)(g * HH + j0 + jj) * HH + k];
        __nv_bfloat16 h = __float2bfloat16(v);
        ((__nv_bfloat16*)(Whi + r * WROWB))[k] = h;
        ((__nv_bfloat16*)(Wlo + r * WROWB))[k] = __float2bfloat16(v - __bfloat162float(h));
    }

    // zero h (parity 0, hi+lo) and c for owned columns
    if (tid < BB) {
        __nv_bfloat16 z = __float2bfloat16(0.f);
#pragma unroll
        for (int jj = 0; jj < JC; jj++) {
            int ci = tid * HH + j0 + jj;
            hb[ci] = z;
            hb[BBHH + ci] = z;
            cst[ci] = 0.f;
        }
    }

    uint32_t hbA = smem_u32(Hb);
    uint32_t psmA = smem_u32(Psm);
    uint32_t wA[2] = { smem_u32(Whi), smem_u32(Wlo) };

    // ldmatrix address components
    int aRow = (lane & 15);
    int aHalf = (lane >> 4) * 16;
    int gB = lane >> 3;
    int fi01 = (gB >> 1) * 8 + (lane & 7);
    int bHalf01 = (gB & 1) * 16;
    int row2 = 16 + (lane & 7);
    int bHalf2 = ((lane >> 3) & 1) * 16;
    int g4 = lane >> 2, tig = lane & 3;

    // ---- flag barrier (arrive own flag, poll flag[tid]) ----
    auto flag_barrier = [&](unsigned target) {
        __threadfence();
        __syncthreads();
        if (tid == 0)
            *(volatile unsigned*)&g_flags[blockIdx.x] = s_base + target;
        unsigned want = s_base + target;
        while ((int)(*(volatile unsigned*)&g_flags[tid] - want) < 0) { }
        __threadfence();
        __syncthreads();
    };

    flag_barrier(1);

    for (int t = 0; t < TT; t++) {
        int pin = t & 1;
        const __nv_bfloat16* hinh = hb + (size_t)(pin * 2 + 0) * BBHH;
        const __nv_bfloat16* hinl = hb + (size_t)(pin * 2 + 1) * BBHH;
        __nv_bfloat16* houth = hb + (size_t)((pin ^ 1) * 2 + 0) * BBHH;
        __nv_bfloat16* houtl = hb + (size_t)((pin ^ 1) * 2 + 1) * BBHH;

        // preamble: pre[t] + chunk0 (one group), chunk1 (second group)
        pre_issue(psmA, pre, t, j0, tid);
        rec_issue(hbA, 0, hinh, hinl, 0, tid);
        cpcommit();
        rec_issue(hbA, 1, hinh, hinl, 64, tid);
        cpcommit();

        float acc[3][4];
#pragma unroll
        for (int f = 0; f < 3; f++)
#pragma unroll
            for (int r = 0; r < 4; r++) acc[f][r] = 0.f;

        for (int c = 0; c < NCHR; c++) {
            int slot = c % 3;
            if (c + 2 < NCHR) {
                rec_issue(hbA, (c + 2) % 3, hinh, hinl, (c + 2) * 64, tid);
                cpcommit();
                cpwait<2>();
            } else if (c + 1 < NCHR) {
                cpwait<1>();
            } else {
                cpwait<0>();
            }
            __syncthreads();
            uint32_t Ahi = hbA + slot * 2 * HTILE;
            uint32_t Alo = Ahi + HTILE;
            uint32_t Whc = wA[0] + c * 128;
            uint32_t Wlc = wA[1] + c * 128;
#pragma unroll
            for (int kk = 0; kk < 4; kk++) {
                uint32_t ah[4], al[4];
                ldsm4(Ahi + (w*16 + aRow) * HROWB + aHalf + kk*32, ah);
                ldsm4(Alo + (w*16 + aRow) * HROWB + aHalf + kk*32, al);
                uint32_t bh01[4], bh2[2], bl01[4], bl2[2];
                ldsm4(Whc + fi01 * WROWB + bHalf01 + kk*32, bh01);
                ldsm2(Whc + row2 * WROWB + bHalf2 + kk*32, bh2);
                ldsm4(Wlc + fi01 * WROWB + bHalf01 + kk*32, bl01);
                ldsm2(Wlc + row2 * WROWB + bHalf2 + kk*32, bl2);
                // h_hi @ W_hi
                mma_bf16(acc[0], ah, bh01[0], bh01[1]);
                mma_bf16(acc[1], ah, bh01[2], bh01[3]);
                mma_bf16(acc[2], ah, bh2[0], bh2[1]);
                // h_hi @ W_lo
                mma_bf16(acc[0], ah, bl01[0], bl01[1]);
                mma_bf16(acc[1], ah, bl01[2], bl01[3]);
                mma_bf16(acc[2], ah, bl2[0], bl2[1]);
                // h_lo @ W_hi
                mma_bf16(acc[0], al, bh01[0], bh01[1]);
                mma_bf16(acc[1], al, bh01[2], bh01[3]);
                mma_bf16(acc[2], al, bh2[0], bh2[1]);
            }
            __syncthreads();
        }

        // write gate tile to Csm: row = batch, col = gate*JC + jj
#pragma unroll
        for (int f = 0; f < 3; f++) {
            Csm[(w*16 + g4) * 28 + f*8 + tig*2]     = acc[f][0];
            Csm[(w*16 + g4) * 28 + f*8 + tig*2 + 1] = acc[f][1];
            Csm[(w*16 + 8 + g4) * 28 + f*8 + tig*2]     = acc[f][2];
            Csm[(w*16 + 8 + g4) * 28 + f*8 + tig*2 + 1] = acc[f][3];
        }
        __syncthreads();

        // cell update: 64 b x JC cols = 384 elems, 3 per thread (pre from SMEM)
#pragma unroll
        for (int r = 0; r < 3; r++) {
            int e = r * 128 + tid;
            int b = e / JC, jj = e - b * JC;
            int j = j0 + jj;
            float gi = Csm[b*28 + 0*JC + jj] + Psm[b*24 + 0*JC + jj];
            float gf = Csm[b*28 + 1*JC + jj] + Psm[b*24 + 1*JC + jj];
            float gg = Csm[b*28 + 2*JC + jj] + Psm[b*24 + 2*JC + jj];
            float go = Csm[b*28 + 3*JC + jj] + Psm[b*24 + 3*JC + jj];
            float si = 1.0f / (1.0f + expf(-gi));
            float sf = 1.0f / (1.0f + expf(-gf));
            float so = 1.0f / (1.0f + expf(-go));
            float tg = tanhf(gg);
            int ci = b * HH + j;
            float cn = sf * cst[ci] + si * tg;
            float hn = so * tanhf(cn);
            cst[ci] = cn;
            __nv_bfloat16 hh = __float2bfloat16(hn);
            houth[ci] = hh;
            houtl[ci] = __float2bfloat16(hn - __bfloat162float(hh));
            size_t yi = ((size_t)b * TT + t) * HH + j;
            y[yi] = res ? hn + res[yi] : hn;
        }
        flag_barrier(t + 2);
    }
}

// ---------------- output copy ----------------
__global__ void copy_out(float* __restrict__ out, const float* __restrict__ proj, int n)
{
    int i = blockIdx.x * blockDim.x + threadIdx.x;
    int stride = gridDim.x * blockDim.x;
    for (; i < n; i += stride) {
        int m = i / OUTD, o = i % OUTD;
        out[i] = proj[(size_t)m * 128 + o];
    }
}

// ---------------- driver ----------------
extern "C" void kernel_launch(void* const* d_in, const int* in_sizes, int n_in,
                              void* d_out, int out_size)
{
    const float* x   = (const float*)d_in[0];
    const float* Wih[3] = { (const float*)d_in[1], (const float*)d_in[4], (const float*)d_in[7] };
    const float* Whh[3] = { (const float*)d_in[2], (const float*)d_in[5], (const float*)d_in[8] };
    const float* bgt[3] = { (const float*)d_in[3], (const float*)d_in[6], (const float*)d_in[9] };
    const float* Wp  = (const float*)d_in[10];

    float *pre, *x1, *x2, *x3, *proj, *cbuf;
    __nv_bfloat16 *ah, *al, *bh, *bl, *pph, *ppl, *hbp;
    cudaGetSymbolAddress((void**)&pre,  g_pre);
    cudaGetSymbolAddress((void**)&x1,   g_x1);
    cudaGetSymbolAddress((void**)&x2,   g_x2);
    cudaGetSymbolAddress((void**)&x3,   g_x3);
    cudaGetSymbolAddress((void**)&proj, g_proj);
    cudaGetSymbolAddress((void**)&cbuf, g_c);
    cudaGetSymbolAddress((void**)&hbp,  g_hb);
    cudaGetSymbolAddress((void**)&ah,   g_ah);
    cudaGetSymbolAddress((void**)&al,   g_al);
    cudaGetSymbolAddress((void**)&bh,   g_bh);
    cudaGetSymbolAddress((void**)&bl,   g_bl);
    cudaGetSymbolAddress((void**)&pph,  g_ph);
    cudaGetSymbolAddress((void**)&ppl,  g_pl);

    cudaFuncSetAttribute(lstm_persist, cudaFuncAttributeMaxDynamicSharedMemorySize, RSMEM);
    cudaFuncSetAttribute(gemm_mma3, cudaFuncAttributeMaxDynamicSharedMemorySize, GSMEM);

    float* xs[3] = { x1, x2, x3 };
    const float* layerIn = x;
    int K = INF;

    for (int L = 0; L < 3; L++) {
        split_bf16<<<4096, 256>>>(layerIn, ah, al, (size_t)MM * K / 4);
        split_bf16<<<512, 256>>>(Wih[L], bh, bl, (size_t)GG * K / 4);

        dim3 grid(GG / 128, MM / 128);
        gemm_mma3<<<grid, 256, GSMEM>>>(ah, al, bh, bl, bgt[L], pre, K, GG);

        const float* res = (L > 0) ? layerIn : nullptr;
        lstm_persist<<<NCTA, 128, RSMEM>>>(pre, Whh[L], hbp, cbuf, xs[L], res);

        layerIn = xs[L];
        K = HH;
    }

    // projection
    split_bf16<<<4096, 256>>>(x3, ah, al, (size_t)MM * HH / 4);
    pad_wp_split<<<96, 256>>>(pph, ppl, Wp);
    dim3 gridP(1, MM / 128);
    gemm_mma3<<<gridP, 256, GSMEM>>>(ah, al, pph, ppl, nullptr, proj, HH, 128);
    copy_out<<<1024, 256>>>((float*)d_out, proj, MM * OUTD);
}

// round 8
// speedup vs baseline: 1.5622x; 1.5622x over previous
#include <cuda_runtime.h>
#include <cuda_bf16.h>
#include <math.h>
#include <stdint.h>

#define BB 64
#define TT 1024
#define INF 512
#define HH 768
#define GG 3072          // 4*H
#define MM (BB*TT)       // 65536
#define OUTD 100
#define BBHH (BB*HH)

// recurrence config
#define NCTA 128
#define JC 6             // h columns per CTA
#define NC 24            // gate rows per CTA (4*JC)
#define NCHR 12          // 768/64 k-chunks
#define WROWB 1552       // W smem row pitch bytes (768*2 + 16)
#define HROWB 144        // h tile row pitch bytes (64*2 + 16)
#define HTILE (64*HROWB) // 9216
#define WTILE (NC*WROWB) // 37248

// GEMM config
#define GAT (128*HROWB)  // 18432 bytes: one 128x64 bf16 tile
#define GSMEM (6*GAT)    // 3 stages x (A,B) = 110592
#define RSMEM (2*WTILE + 6*HTILE + 64*28*4)  // 136960

// ---------------- scratch (device globals; no allocation allowed) ----------------
__device__ float g_pre[(size_t)MM * GG];
__device__ float g_x1[(size_t)MM * HH];
__device__ float g_x2[(size_t)MM * HH];
__device__ float g_x3[(size_t)MM * HH];
__device__ float g_proj[(size_t)MM * 128];
__device__ float g_c[BBHH];
__device__ __nv_bfloat16 g_hb[2][2][BBHH];   // [parity][hi/lo]
__device__ unsigned g_count = 0;             // grid barrier arrivals
__device__ unsigned g_epoch = 0;             // grid barrier epoch (monotonic)
// bf16 split buffers
__device__ __nv_bfloat16 g_ah[(size_t)MM * HH];
__device__ __nv_bfloat16 g_al[(size_t)MM * HH];
__device__ __nv_bfloat16 g_bh[(size_t)GG * HH];
__device__ __nv_bfloat16 g_bl[(size_t)GG * HH];
__device__ __nv_bfloat16 g_ph[128 * HH];
__device__ __nv_bfloat16 g_pl[128 * HH];

// ---------------- ptx helpers (base sm_103 ISA only) ----------------
__device__ __forceinline__ void cpasync16(uint32_t saddr, const void* g) {
    asm volatile("cp.async.cg.shared.global [%0], [%1], 16;\n" :: "r"(saddr), "l"(g));
}
__device__ __forceinline__ void cpcommit() { asm volatile("cp.async.commit_group;\n"); }
template<int N> __device__ __forceinline__ void cpwait() {
    asm volatile("cp.async.wait_group %0;\n" :: "n"(N));
}
__device__ __forceinline__ uint32_t smem_u32(const void* p) {
    return (uint32_t)__cvta_generic_to_shared(p);
}
__device__ __forceinline__ void ldsm4(uint32_t addr, uint32_t* r) {
    asm volatile("ldmatrix.sync.aligned.m8n8.x4.shared.b16 {%0,%1,%2,%3}, [%4];"
                 : "=r"(r[0]), "=r"(r[1]), "=r"(r[2]), "=r"(r[3]) : "r"(addr));
}
__device__ __forceinline__ void ldsm2(uint32_t addr, uint32_t* r) {
    asm volatile("ldmatrix.sync.aligned.m8n8.x2.shared.b16 {%0,%1}, [%2];"
                 : "=r"(r[0]), "=r"(r[1]) : "r"(addr));
}
__device__ __forceinline__ void mma_bf16(float* d, const uint32_t* a, uint32_t b0, uint32_t b1) {
    asm volatile(
        "mma.sync.aligned.m16n8k16.row.col.f32.bf16.bf16.f32 "
        "{%0,%1,%2,%3}, {%4,%5,%6,%7}, {%8,%9}, {%0,%1,%2,%3};"
        : "+f"(d[0]), "+f"(d[1]), "+f"(d[2]), "+f"(d[3])
        : "r"(a[0]), "r"(a[1]), "r"(a[2]), "r"(a[3]), "r"(b0), "r"(b1));
}

// ---------------- software grid barrier (R6-proven atomic version) ----------------
__device__ __forceinline__ void grid_barrier(unsigned e0, unsigned target) {
    __threadfence();
    __syncthreads();
    if (threadIdx.x == 0) {
        unsigned a = atomicAdd(&g_count, 1);
        if (a == NCTA - 1) {
            g_count = 0;
            __threadfence();
            atomicAdd(&g_epoch, 1);
        } else {
            while ((*(volatile unsigned*)&g_epoch) - e0 < target) { }
            __threadfence();
        }
    }
    __syncthreads();
}

// ---------------- bf16 split conversions ----------------
__global__ void split_bf16(const float* __restrict__ src,
                           __nv_bfloat16* __restrict__ hi,
                           __nv_bfloat16* __restrict__ lo, size_t n4)
{
    size_t i = (size_t)blockIdx.x * blockDim.x + threadIdx.x;
    size_t stride = (size_t)gridDim.x * blockDim.x;
    for (; i < n4; i += stride) {
        float4 v = ((const float4*)src)[i];
        __nv_bfloat16 h0 = __float2bfloat16(v.x);
        __nv_bfloat16 h1 = __float2bfloat16(v.y);
        __nv_bfloat16 h2 = __float2bfloat16(v.z);
        __nv_bfloat16 h3 = __float2bfloat16(v.w);
        __nv_bfloat162 hp0; hp0.x = h0; hp0.y = h1;
        __nv_bfloat162 hp1; hp1.x = h2; hp1.y = h3;
        __nv_bfloat162 lp0;
        lp0.x = __float2bfloat16(v.x - __bfloat162float(h0));
        lp0.y = __float2bfloat16(v.y - __bfloat162float(h1));
        __nv_bfloat162 lp1;
        lp1.x = __float2bfloat16(v.z - __bfloat162float(h2));
        lp1.y = __float2bfloat16(v.w - __bfloat162float(h3));
        ((__nv_bfloat162*)hi)[2*i]   = hp0;
        ((__nv_bfloat162*)hi)[2*i+1] = hp1;
        ((__nv_bfloat162*)lo)[2*i]   = lp0;
        ((__nv_bfloat162*)lo)[2*i+1] = lp1;
    }
}

__global__ void pad_wp_split(__nv_bfloat16* __restrict__ ph,
                             __nv_bfloat16* __restrict__ pl,
                             const float* __restrict__ Wp)
{
    int i = blockIdx.x * blockDim.x + threadIdx.x;
    int stride = gridDim.x * blockDim.x;
    for (; i < 128 * HH; i += stride) {
        int o = i / HH, k = i % HH;
        float v = (o < OUTD) ? Wp[o * HH + k] : 0.f;
        __nv_bfloat16 h = __float2bfloat16(v);
        ph[i] = h;
        pl[i] = __float2bfloat16(v - __bfloat162float(h));
    }
}

// ---------------- bf16x3 GEMM via mma.sync (ring-3 pipeline, R7 version) ----------------
__device__ __forceinline__ void gemm_issue(uint32_t sb, int stage,
                                           const __nv_bfloat16* Ag,
                                           const __nv_bfloat16* Bg,
                                           int K, int tid)
{
    uint32_t dA = sb + stage * 2 * GAT;
    uint32_t dB = dA + GAT;
#pragma unroll
    for (int it = 0; it < 4; it++) {
        int idx = it * 256 + tid;
        int row = idx >> 3, seg = idx & 7;
        cpasync16(dA + row * HROWB + seg * 16, Ag + (size_t)row * K + seg * 8);
    }
#pragma unroll
    for (int it = 0; it < 4; it++) {
        int idx = it * 256 + tid;
        int row = idx >> 3, seg = idx & 7;
        cpasync16(dB + row * HROWB + seg * 16, Bg + (size_t)row * K + seg * 8);
    }
    cpcommit();
}

__global__ __launch_bounds__(256)
void gemm_mma3(const __nv_bfloat16* __restrict__ Ah, const __nv_bfloat16* __restrict__ Al,
               const __nv_bfloat16* __restrict__ Bh, const __nv_bfloat16* __restrict__ Bl,
               const float* __restrict__ bias, float* __restrict__ C,
               int K, int Ntot)
{
    extern __shared__ __align__(128) char gsm[];
    uint32_t sb = smem_u32(gsm);

    int tid = threadIdx.x;
    int lane = tid & 31;
    int wid = tid >> 5;
    int wm = wid & 3;
    int wn = wid >> 2;
    int m0 = blockIdx.y * 128;
    int n0 = blockIdx.x * 128;

    const __nv_bfloat16* As_[3] = { Ah, Ah, Al };
    const __nv_bfloat16* Bs_[3] = { Bh, Bl, Bh };
    const int cps = K >> 6;
    const int nch = 3 * cps;

    float acc[2][8][4];
#pragma unroll
    for (int mt = 0; mt < 2; mt++)
#pragma unroll
        for (int f = 0; f < 8; f++)
#pragma unroll
            for (int r = 0; r < 4; r++) acc[mt][f][r] = 0.f;

    int aRow = (lane & 15);
    int aHalf = (lane >> 4) * 16;
    int gB = lane >> 3;
    int bHalf = (gB & 1) * 16;

    {
        gemm_issue(sb, 0, As_[0] + (size_t)m0 * K, Bs_[0] + (size_t)n0 * K, K, tid);
        int s1 = 1 / cps, ck1 = (1 - s1 * cps) * 64;
        gemm_issue(sb, 1, As_[s1] + (size_t)m0 * K + ck1, Bs_[s1] + (size_t)n0 * K + ck1, K, tid);
    }

    for (int c = 0; c < nch; c++) {
        int stage = c % 3;
        if (c + 2 < nch) {
            int cn = c + 2;
            int s = cn / cps, ck = (cn - s * cps) * 64;
            gemm_issue(sb, (c + 2) % 3, As_[s] + (size_t)m0 * K + ck,
                       Bs_[s] + (size_t)n0 * K + ck, K, tid);
            cpwait<2>();
        } else if (c + 1 < nch) {
            cpwait<1>();
        } else {
            cpwait<0>();
        }
        __syncthreads();
        uint32_t A = sb + stage * 2 * GAT;
        uint32_t B = A + GAT;
#pragma unroll
        for (int kk = 0; kk < 4; kk++) {
            uint32_t a[2][4];
#pragma unroll
            for (int mt = 0; mt < 2; mt++)
                ldsm4(A + (wm*32 + mt*16 + aRow) * HROWB + aHalf + kk*32, a[mt]);
            uint32_t bfr[8][2];
#pragma unroll
            for (int fp = 0; fp < 4; fp++) {
                int fi = fp * 2 + (gB >> 1);
                uint32_t r4[4];
                ldsm4(B + (wn*64 + fi*8 + (lane & 7)) * HROWB + bHalf + kk*32, r4);
                bfr[fp*2][0]   = r4[0]; bfr[fp*2][1]   = r4[1];
                bfr[fp*2+1][0] = r4[2]; bfr[fp*2+1][1] = r4[3];
            }
#pragma unroll
            for (int mt = 0; mt < 2; mt++)
#pragma unroll
                for (int f = 0; f < 8; f++)
                    mma_bf16(acc[mt][f], a[mt], bfr[f][0], bfr[f][1]);
        }
        __syncthreads();
    }

    int g4 = lane >> 2, tig = lane & 3;
#pragma unroll
    for (int mt = 0; mt < 2; mt++) {
#pragma unroll
        for (int f = 0; f < 8; f++) {
            int r0 = m0 + wm*32 + mt*16 + g4;
            int c0 = n0 + wn*64 + f*8 + tig*2;
            float b0 = bias ? bias[c0] : 0.f;
            float b1 = bias ? bias[c0+1] : 0.f;
            float2 v0; v0.x = acc[mt][f][0] + b0; v0.y = acc[mt][f][1] + b1;
            float2 v1; v1.x = acc[mt][f][2] + b0; v1.y = acc[mt][f][3] + b1;
            *(float2*)&C[(size_t)r0 * Ntot + c0] = v0;
            *(float2*)&C[(size_t)(r0 + 8) * Ntot + c0] = v1;
        }
    }
}

// ---------------- persistent LSTM with mma recurrence ----------------
__device__ __forceinline__ void rec_issue(uint32_t hbA, int slot,
                                          const __nv_bfloat16* hhi,
                                          const __nv_bfloat16* hlo,
                                          int k0, int tid)
{
    uint32_t dH = hbA + slot * 2 * HTILE;
    uint32_t dL = dH + HTILE;
#pragma unroll
    for (int it = 0; it < 4; it++) {
        int idx = it * 128 + tid;
        int row = idx >> 3, seg = idx & 7;
        cpasync16(dH + row * HROWB + seg * 16, hhi + (size_t)row * HH + k0 + seg * 8);
        cpasync16(dL + row * HROWB + seg * 16, hlo + (size_t)row * HH + k0 + seg * 8);
    }
    cpcommit();
}

__global__ __launch_bounds__(128, 1)
void lstm_persist(const float* __restrict__ pre, const float* __restrict__ Whh,
                  __nv_bfloat16* __restrict__ hb, float* __restrict__ cst,
                  float* __restrict__ y, const float* __restrict__ res)
{
    extern __shared__ __align__(128) char rsm[];
    char* Whi = rsm;
    char* Wlo = rsm + WTILE;
    char* Hb  = rsm + 2 * WTILE;                       // ring of 3 x (hi+lo)
    float* Csm = (float*)(rsm + 2 * WTILE + 6 * HTILE);

    int tid = threadIdx.x;
    int lane = tid & 31;
    int w = tid >> 5;
    int j0 = blockIdx.x * JC;
    unsigned e0 = 0;
    if (tid == 0) e0 = *(volatile unsigned*)&g_epoch;

    // cache Whh slice as bf16 hi/lo. SMEM row r = gate r/JC, col j0 + r%JC.
    for (int i = tid; i < NC * HH; i += 128) {
        int r = i / HH, k = i - r * HH;
        int g = r / JC, jj = r - g * JC;
        float v = Whh[(size_t)(g * HH + j0 + jj) * HH + k];
        __nv_bfloat16 h = __float2bfloat16(v);
        ((__nv_bfloat16*)(Whi + r * WROWB))[k] = h;
        ((__nv_bfloat16*)(Wlo + r * WROWB))[k] = __float2bfloat16(v - __bfloat162float(h));
    }

    // zero h (parity 0, hi+lo) and c for owned columns
    if (tid < BB) {
        __nv_bfloat16 z = __float2bfloat16(0.f);
#pragma unroll
        for (int jj = 0; jj < JC; jj++) {
            int ci = tid * HH + j0 + jj;
            hb[ci] = z;
            hb[BBHH + ci] = z;
            cst[ci] = 0.f;
        }
    }
    grid_barrier(e0, 1);

    uint32_t hbA = smem_u32(Hb);
    uint32_t wA[2] = { smem_u32(Whi), smem_u32(Wlo) };

    // ldmatrix address components (R6-proven layout)
    int aRow = (lane & 15);
    int aHalf = (lane >> 4) * 16;
    int gB = lane >> 3;
    int fi01 = (gB >> 1) * 8 + (lane & 7);
    int bHalf01 = (gB & 1) * 16;
    int row2 = 16 + (lane & 7);
    int bHalf2 = ((lane >> 3) & 1) * 16;
    int g4 = lane >> 2, tig = lane & 3;

    const int paA[3] = { 0, 0, 1 };
    const int paW[3] = { 0, 1, 0 };

    // cell-update partition (for pre/res register preload)
    int eb[3], ejj[3];
#pragma unroll
    for (int r = 0; r < 3; r++) {
        int e = r * 128 + tid;
        eb[r] = e / JC;
        ejj[r] = e - eb[r] * JC;
    }

    for (int t = 0; t < TT; t++) {
        int pin = t & 1;
        const __nv_bfloat16* hinh = hb + (size_t)(pin * 2 + 0) * BBHH;
        const __nv_bfloat16* hinl = hb + (size_t)(pin * 2 + 1) * BBHH;
        __nv_bfloat16* houth = hb + (size_t)((pin ^ 1) * 2 + 0) * BBHH;
        __nv_bfloat16* houtl = hb + (size_t)((pin ^ 1) * 2 + 1) * BBHH;

        // preamble: issue chunks 0 and 1
        rec_issue(hbA, 0, hinh, hinl, 0, tid);
        rec_issue(hbA, 1, hinh, hinl, 64, tid);

        // preload pre[t] (and res[t]) into registers; consumed after mma loop.
        float preg[3][4], resv[3];
#pragma unroll
        for (int r = 0; r < 3; r++) {
            int b = eb[r], j = j0 + ejj[r];
            size_t prow = ((size_t)b * TT + t) * GG;
            preg[r][0] = pre[prow + 0*HH + j];
            preg[r][1] = pre[prow + 1*HH + j];
            preg[r][2] = pre[prow + 2*HH + j];
            preg[r][3] = pre[prow + 3*HH + j];
            resv[r] = res ? res[((size_t)b * TT + t) * HH + j] : 0.f;
        }

        float acc[3][4];
#pragma unroll
        for (int f = 0; f < 3; f++)
#pragma unroll
            for (int r = 0; r < 4; r++) acc[f][r] = 0.f;

        for (int c = 0; c < NCHR; c++) {
            int slot = c % 3;
            if (c + 2 < NCHR) {
                rec_issue(hbA, (c + 2) % 3, hinh, hinl, (c + 2) * 64, tid);
                cpwait<2>();
            } else if (c + 1 < NCHR) {
                cpwait<1>();
            } else {
                cpwait<0>();
            }
            __syncthreads();
            uint32_t Ab[2];
            Ab[0] = hbA + slot * 2 * HTILE;
            Ab[1] = Ab[0] + HTILE;
#pragma unroll
            for (int p = 0; p < 3; p++) {
                uint32_t Abase = Ab[paA[p]];
                uint32_t Wbase = wA[paW[p]] + c * 128;
#pragma unroll
                for (int kk = 0; kk < 4; kk++) {
                    uint32_t a[4];
                    ldsm4(Abase + (w*16 + aRow) * HROWB + aHalf + kk*32, a);
                    uint32_t b01[4];
                    ldsm4(Wbase + fi01 * WROWB + bHalf01 + kk*32, b01);
                    uint32_t b2[2];
                    ldsm2(Wbase + row2 * WROWB + bHalf2 + kk*32, b2);
                    mma_bf16(acc[0], a, b01[0], b01[1]);
                    mma_bf16(acc[1], a, b01[2], b01[3]);
                    mma_bf16(acc[2], a, b2[0], b2[1]);
                }
            }
            __syncthreads();
        }

        // write gate tile to Csm: row = batch, col = gate*JC + jj
#pragma unroll
        for (int f = 0; f < 3; f++) {
            Csm[(w*16 + g4) * 28 + f*8 + tig*2]     = acc[f][0];
            Csm[(w*16 + g4) * 28 + f*8 + tig*2 + 1] = acc[f][1];
            Csm[(w*16 + 8 + g4) * 28 + f*8 + tig*2]     = acc[f][2];
            Csm[(w*16 + 8 + g4) * 28 + f*8 + tig*2 + 1] = acc[f][3];
        }
        __syncthreads();

        // cell update: 64 b x JC cols = 384 elems, 3 per thread
#pragma unroll
        for (int r = 0; r < 3; r++) {
            int b = eb[r], jj = ejj[r];
            int j = j0 + jj;
            float gi = Csm[b*28 + 0*JC + jj] + preg[r][0];
            float gf = Csm[b*28 + 1*JC + jj] + preg[r][1];
            float gg = Csm[b*28 + 2*JC + jj] + preg[r][2];
            float go = Csm[b*28 + 3*JC + jj] + preg[r][3];
            float si = 1.0f / (1.0f + expf(-gi));
            float sf = 1.0f / (1.0f + expf(-gf));
            float so = 1.0f / (1.0f + expf(-go));
            float tg = tanhf(gg);
            int ci = b * HH + j;
            float cn = sf * cst[ci] + si * tg;
            float hn = so * tanhf(cn);
            cst[ci] = cn;
            __nv_bfloat16 hh = __float2bfloat16(hn);
            houth[ci] = hh;
            houtl[ci] = __float2bfloat16(hn - __bfloat162float(hh));
            size_t yi = ((size_t)b * TT + t) * HH + j;
            y[yi] = res ? hn + resv[r] : hn;
        }
        grid_barrier(e0, t + 2);
    }
}

// ---------------- output copy ----------------
__global__ void copy_out(float* __restrict__ out, const float* __restrict__ proj, int n)
{
    int i = blockIdx.x * blockDim.x + threadIdx.x;
    int stride = gridDim.x * blockDim.x;
    for (; i < n; i += stride) {
        int m = i / OUTD, o = i % OUTD;
        out[i] = proj[(size_t)m * 128 + o];
    }
}

// ---------------- driver ----------------
extern "C" void kernel_launch(void* const* d_in, const int* in_sizes, int n_in,
                              void* d_out, int out_size)
{
    const float* x   = (const float*)d_in[0];
    const float* Wih[3] = { (const float*)d_in[1], (const float*)d_in[4], (const float*)d_in[7] };
    const float* Whh[3] = { (const float*)d_in[2], (const float*)d_in[5], (const float*)d_in[8] };
    const float* bgt[3] = { (const float*)d_in[3], (const float*)d_in[6], (const float*)d_in[9] };
    const float* Wp  = (const float*)d_in[10];

    float *pre, *x1, *x2, *x3, *proj, *cbuf;
    __nv_bfloat16 *ah, *al, *bh, *bl, *pph, *ppl, *hbp;
    cudaGetSymbolAddress((void**)&pre,  g_pre);
    cudaGetSymbolAddress((void**)&x1,   g_x1);
    cudaGetSymbolAddress((void**)&x2,   g_x2);
    cudaGetSymbolAddress((void**)&x3,   g_x3);
    cudaGetSymbolAddress((void**)&proj, g_proj);
    cudaGetSymbolAddress((void**)&cbuf, g_c);
    cudaGetSymbolAddress((void**)&hbp,  g_hb);
    cudaGetSymbolAddress((void**)&ah,   g_ah);
    cudaGetSymbolAddress((void**)&al,   g_al);
    cudaGetSymbolAddress((void**)&bh,   g_bh);
    cudaGetSymbolAddress((void**)&bl,   g_bl);
    cudaGetSymbolAddress((void**)&pph,  g_ph);
    cudaGetSymbolAddress((void**)&ppl,  g_pl);

    cudaFuncSetAttribute(lstm_persist, cudaFuncAttributeMaxDynamicSharedMemorySize, RSMEM);
    cudaFuncSetAttribute(gemm_mma3, cudaFuncAttributeMaxDynamicSharedMemorySize, GSMEM);

    float* xs[3] = { x1, x2, x3 };
    const float* layerIn = x;
    int K = INF;

    for (int L = 0; L < 3; L++) {
        split_bf16<<<4096, 256>>>(layerIn, ah, al, (size_t)MM * K / 4);
        split_bf16<<<512, 256>>>(Wih[L], bh, bl, (size_t)GG * K / 4);

        dim3 grid(GG / 128, MM / 128);
        gemm_mma3<<<grid, 256, GSMEM>>>(ah, al, bh, bl, bgt[L], pre, K, GG);

        const float* res = (L > 0) ? layerIn : nullptr;
        lstm_persist<<<NCTA, 128, RSMEM>>>(pre, Whh[L], hbp, cbuf, xs[L], res);

        layerIn = xs[L];
        K = HH;
    }

    // projection
    split_bf16<<<4096, 256>>>(x3, ah, al, (size_t)MM * HH / 4);
    pad_wp_split<<<96, 256>>>(pph, ppl, Wp);
    dim3 gridP(1, MM / 128);
    gemm_mma3<<<gridP, 256, GSMEM>>>(ah, al, pph, ppl, nullptr, proj, HH, 128);
    copy_out<<<1024, 256>>>((float*)d_out, proj, MM * OUTD);
}

// round 9
// speedup vs baseline: 1.7903x; 1.1460x over previous
#include <cuda_runtime.h>
#include <cuda_bf16.h>
#include <math.h>
#include <stdint.h>

#define BB 64
#define TT 1024
#define INF 512
#define HH 768
#define GG 3072          // 4*H
#define MM (BB*TT)       // 65536
#define OUTD 100
#define BBHH (BB*HH)

// recurrence config
#define NCTA 128
#define JC 6             // h columns per CTA
#define NC 24            // gate rows per CTA (4*JC)
#define KCH 128          // k per chunk
#define NCHR 6           // 768/128 chunks
#define WROWB 1552       // W smem row pitch bytes (768*2 + 16)
#define HROW2 272        // h tile row pitch bytes (128*2 + 16)
#define HTILE2 (64*HROW2) // 17408
#define WTILE (NC*WROWB) // 37248

// GEMM config
#define HROWB 144        // GEMM tile row pitch (64*2 + 16)
#define GAT (128*HROWB)  // 18432 bytes: one 128x64 bf16 tile
#define GSMEM (6*GAT)    // 3 stages x (A,B) = 110592
#define RSMEM (2*WTILE + 6*HTILE2 + 64*28*4)  // 186112

// ---------------- scratch (device globals; no allocation allowed) ----------------
__device__ float g_pre[(size_t)MM * GG];
__device__ float g_x1[(size_t)MM * HH];
__device__ float g_x2[(size_t)MM * HH];
__device__ float g_x3[(size_t)MM * HH];
__device__ float g_proj[(size_t)MM * 128];
__device__ __nv_bfloat16 g_hb[2][2][BBHH];   // [parity][hi/lo]
__device__ unsigned g_count = 0;             // grid barrier arrivals
__device__ unsigned g_epoch = 0;             // grid barrier epoch (monotonic)
// bf16 split buffers
__device__ __nv_bfloat16 g_ah[(size_t)MM * HH];
__device__ __nv_bfloat16 g_al[(size_t)MM * HH];
__device__ __nv_bfloat16 g_bh[(size_t)GG * HH];
__device__ __nv_bfloat16 g_bl[(size_t)GG * HH];
__device__ __nv_bfloat16 g_ph[128 * HH];
__device__ __nv_bfloat16 g_pl[128 * HH];

// ---------------- ptx helpers (base sm_103 ISA only) ----------------
__device__ __forceinline__ void cpasync16(uint32_t saddr, const void* g) {
    asm volatile("cp.async.cg.shared.global [%0], [%1], 16;\n" :: "r"(saddr), "l"(g));
}
__device__ __forceinline__ void cpcommit() { asm volatile("cp.async.commit_group;\n"); }
template<int N> __device__ __forceinline__ void cpwait() {
    asm volatile("cp.async.wait_group %0;\n" :: "n"(N));
}
__device__ __forceinline__ uint32_t smem_u32(const void* p) {
    return (uint32_t)__cvta_generic_to_shared(p);
}
__device__ __forceinline__ void ldsm4(uint32_t addr, uint32_t* r) {
    asm volatile("ldmatrix.sync.aligned.m8n8.x4.shared.b16 {%0,%1,%2,%3}, [%4];"
                 : "=r"(r[0]), "=r"(r[1]), "=r"(r[2]), "=r"(r[3]) : "r"(addr));
}
__device__ __forceinline__ void ldsm2(uint32_t addr, uint32_t* r) {
    asm volatile("ldmatrix.sync.aligned.m8n8.x2.shared.b16 {%0,%1}, [%2];"
                 : "=r"(r[0]), "=r"(r[1]) : "r"(addr));
}
__device__ __forceinline__ void mma_bf16(float* d, const uint32_t* a, uint32_t b0, uint32_t b1) {
    asm volatile(
        "mma.sync.aligned.m16n8k16.row.col.f32.bf16.bf16.f32 "
        "{%0,%1,%2,%3}, {%4,%5,%6,%7}, {%8,%9}, {%0,%1,%2,%3};"
        : "+f"(d[0]), "+f"(d[1]), "+f"(d[2]), "+f"(d[3])
        : "r"(a[0]), "r"(a[1]), "r"(a[2]), "r"(a[3]), "r"(b0), "r"(b1));
}

// fast sigmoid / tanh (clamped, no-NaN; err ~1e-6)
__device__ __forceinline__ float fsigmoid(float x) {
    return __fdividef(1.f, 1.f + __expf(-x));
}
__device__ __forceinline__ float ftanh(float x) {
    x = fminf(15.f, fmaxf(-15.f, x));
    float e2 = __expf(2.f * x);
    return __fdividef(e2 - 1.f, e2 + 1.f);
}

// ---------------- software grid barrier (R6-proven atomic version) ----------------
__device__ __forceinline__ void grid_barrier(unsigned e0, unsigned target) {
    __threadfence();
    __syncthreads();
    if (threadIdx.x == 0) {
        unsigned a = atomicAdd(&g_count, 1);
        if (a == NCTA - 1) {
            g_count = 0;
            __threadfence();
            atomicAdd(&g_epoch, 1);
        } else {
            while ((*(volatile unsigned*)&g_epoch) - e0 < target) { }
            __threadfence();
        }
    }
    __syncthreads();
}

// ---------------- bf16 split conversions ----------------
__global__ void split_bf16(const float* __restrict__ src,
                           __nv_bfloat16* __restrict__ hi,
                           __nv_bfloat16* __restrict__ lo, size_t n4)
{
    size_t i = (size_t)blockIdx.x * blockDim.x + threadIdx.x;
    size_t stride = (size_t)gridDim.x * blockDim.x;
    for (; i < n4; i += stride) {
        float4 v = ((const float4*)src)[i];
        __nv_bfloat16 h0 = __float2bfloat16(v.x);
        __nv_bfloat16 h1 = __float2bfloat16(v.y);
        __nv_bfloat16 h2 = __float2bfloat16(v.z);
        __nv_bfloat16 h3 = __float2bfloat16(v.w);
        __nv_bfloat162 hp0; hp0.x = h0; hp0.y = h1;
        __nv_bfloat162 hp1; hp1.x = h2; hp1.y = h3;
        __nv_bfloat162 lp0;
        lp0.x = __float2bfloat16(v.x - __bfloat162float(h0));
        lp0.y = __float2bfloat16(v.y - __bfloat162float(h1));
        __nv_bfloat162 lp1;
        lp1.x = __float2bfloat16(v.z - __bfloat162float(h2));
        lp1.y = __float2bfloat16(v.w - __bfloat162float(h3));
        ((__nv_bfloat162*)hi)[2*i]   = hp0;
        ((__nv_bfloat162*)hi)[2*i+1] = hp1;
        ((__nv_bfloat162*)lo)[2*i]   = lp0;
        ((__nv_bfloat162*)lo)[2*i+1] = lp1;
    }
}

__global__ void pad_wp_split(__nv_bfloat16* __restrict__ ph,
                             __nv_bfloat16* __restrict__ pl,
                             const float* __restrict__ Wp)
{
    int i = blockIdx.x * blockDim.x + threadIdx.x;
    int stride = gridDim.x * blockDim.x;
    for (; i < 128 * HH; i += stride) {
        int o = i / HH, k = i % HH;
        float v = (o < OUTD) ? Wp[o * HH + k] : 0.f;
        __nv_bfloat16 h = __float2bfloat16(v);
        ph[i] = h;
        pl[i] = __float2bfloat16(v - __bfloat162float(h));
    }
}

// ---------------- bf16x3 GEMM via mma.sync (ring-3 pipeline, R8 version) ----------------
__device__ __forceinline__ void gemm_issue(uint32_t sb, int stage,
                                           const __nv_bfloat16* Ag,
                                           const __nv_bfloat16* Bg,
                                           int K, int tid)
{
    uint32_t dA = sb + stage * 2 * GAT;
    uint32_t dB = dA + GAT;
#pragma unroll
    for (int it = 0; it < 4; it++) {
        int idx = it * 256 + tid;
        int row = idx >> 3, seg = idx & 7;
        cpasync16(dA + row * HROWB + seg * 16, Ag + (size_t)row * K + seg * 8);
    }
#pragma unroll
    for (int it = 0; it < 4; it++) {
        int idx = it * 256 + tid;
        int row = idx >> 3, seg = idx & 7;
        cpasync16(dB + row * HROWB + seg * 16, Bg + (size_t)row * K + seg * 8);
    }
    cpcommit();
}

__global__ __launch_bounds__(256)
void gemm_mma3(const __nv_bfloat16* __restrict__ Ah, const __nv_bfloat16* __restrict__ Al,
               const __nv_bfloat16* __restrict__ Bh, const __nv_bfloat16* __restrict__ Bl,
               const float* __restrict__ bias, float* __restrict__ C,
               int K, int Ntot)
{
    extern __shared__ __align__(128) char gsm[];
    uint32_t sb = smem_u32(gsm);

    int tid = threadIdx.x;
    int lane = tid & 31;
    int wid = tid >> 5;
    int wm = wid & 3;
    int wn = wid >> 2;
    int m0 = blockIdx.y * 128;
    int n0 = blockIdx.x * 128;

    const __nv_bfloat16* As_[3] = { Ah, Ah, Al };
    const __nv_bfloat16* Bs_[3] = { Bh, Bl, Bh };
    const int cps = K >> 6;
    const int nch = 3 * cps;

    float acc[2][8][4];
#pragma unroll
    for (int mt = 0; mt < 2; mt++)
#pragma unroll
        for (int f = 0; f < 8; f++)
#pragma unroll
            for (int r = 0; r < 4; r++) acc[mt][f][r] = 0.f;

    int aRow = (lane & 15);
    int aHalf = (lane >> 4) * 16;
    int gB = lane >> 3;
    int bHalf = (gB & 1) * 16;

    {
        gemm_issue(sb, 0, As_[0] + (size_t)m0 * K, Bs_[0] + (size_t)n0 * K, K, tid);
        int s1 = 1 / cps, ck1 = (1 - s1 * cps) * 64;
        gemm_issue(sb, 1, As_[s1] + (size_t)m0 * K + ck1, Bs_[s1] + (size_t)n0 * K + ck1, K, tid);
    }

    for (int c = 0; c < nch; c++) {
        int stage = c % 3;
        if (c + 2 < nch) {
            int cn = c + 2;
            int s = cn / cps, ck = (cn - s * cps) * 64;
            gemm_issue(sb, (c + 2) % 3, As_[s] + (size_t)m0 * K + ck,
                       Bs_[s] + (size_t)n0 * K + ck, K, tid);
            cpwait<2>();
        } else if (c + 1 < nch) {
            cpwait<1>();
        } else {
            cpwait<0>();
        }
        __syncthreads();
        uint32_t A = sb + stage * 2 * GAT;
        uint32_t B = A + GAT;
#pragma unroll
        for (int kk = 0; kk < 4; kk++) {
            uint32_t a[2][4];
#pragma unroll
            for (int mt = 0; mt < 2; mt++)
                ldsm4(A + (wm*32 + mt*16 + aRow) * HROWB + aHalf + kk*32, a[mt]);
            uint32_t bfr[8][2];
#pragma unroll
            for (int fp = 0; fp < 4; fp++) {
                int fi = fp * 2 + (gB >> 1);
                uint32_t r4[4];
                ldsm4(B + (wn*64 + fi*8 + (lane & 7)) * HROWB + bHalf + kk*32, r4);
                bfr[fp*2][0]   = r4[0]; bfr[fp*2][1]   = r4[1];
                bfr[fp*2+1][0] = r4[2]; bfr[fp*2+1][1] = r4[3];
            }
#pragma unroll
            for (int mt = 0; mt < 2; mt++)
#pragma unroll
                for (int f = 0; f < 8; f++)
                    mma_bf16(acc[mt][f], a[mt], bfr[f][0], bfr[f][1]);
        }
        __syncthreads();
    }

    int g4 = lane >> 2, tig = lane & 3;
#pragma unroll
    for (int mt = 0; mt < 2; mt++) {
#pragma unroll
        for (int f = 0; f < 8; f++) {
            int r0 = m0 + wm*32 + mt*16 + g4;
            int c0 = n0 + wn*64 + f*8 + tig*2;
            float b0 = bias ? bias[c0] : 0.f;
            float b1 = bias ? bias[c0+1] : 0.f;
            float2 v0; v0.x = acc[mt][f][0] + b0; v0.y = acc[mt][f][1] + b1;
            float2 v1; v1.x = acc[mt][f][2] + b0; v1.y = acc[mt][f][3] + b1;
            *(float2*)&C[(size_t)r0 * Ntot + c0] = v0;
            *(float2*)&C[(size_t)(r0 + 8) * Ntot + c0] = v1;
        }
    }
}

// ---------------- persistent LSTM with mma recurrence ----------------
// 128-k chunks: 6 chunks per step, ring-3.
__device__ __forceinline__ void rec_issue(uint32_t hbA, int slot,
                                          const __nv_bfloat16* hhi,
                                          const __nv_bfloat16* hlo,
                                          int k0, int tid)
{
    uint32_t dH = hbA + slot * 2 * HTILE2;
    uint32_t dL = dH + HTILE2;
#pragma unroll
    for (int it = 0; it < 8; it++) {
        int idx = it * 128 + tid;         // 1024 granules per matrix
        int row = idx >> 4, seg = idx & 15;
        cpasync16(dH + row * HROW2 + seg * 16, hhi + (size_t)row * HH + k0 + seg * 8);
        cpasync16(dL + row * HROW2 + seg * 16, hlo + (size_t)row * HH + k0 + seg * 8);
    }
    cpcommit();
}

__global__ __launch_bounds__(128, 1)
void lstm_persist(const float* __restrict__ pre, const float* __restrict__ Whh,
                  __nv_bfloat16* __restrict__ hb,
                  float* __restrict__ y, const float* __restrict__ res)
{
    extern __shared__ __align__(128) char rsm[];
    char* Whi = rsm;
    char* Wlo = rsm + WTILE;
    char* Hb  = rsm + 2 * WTILE;                        // ring of 3 x (hi+lo)
    float* Csm = (float*)(rsm + 2 * WTILE + 6 * HTILE2);

    int tid = threadIdx.x;
    int lane = tid & 31;
    int w = tid >> 5;
    int j0 = blockIdx.x * JC;
    unsigned e0 = 0;
    if (tid == 0) e0 = *(volatile unsigned*)&g_epoch;

    // cache Whh slice as bf16 hi/lo. SMEM row r = gate r/JC, col j0 + r%JC.
    for (int i = tid; i < NC * HH; i += 128) {
        int r = i / HH, k = i - r * HH;
        int g = r / JC, jj = r - g * JC;
        float v = Whh[(size_t)(g * HH + j0 + jj) * HH + k];
        __nv_bfloat16 h = __float2bfloat16(v);
        ((__nv_bfloat16*)(Whi + r * WROWB))[k] = h;
        ((__nv_bfloat16*)(Wlo + r * WROWB))[k] = __float2bfloat16(v - __bfloat162float(h));
    }

    // zero h (parity 0, hi+lo) for owned columns
    if (tid < BB) {
        __nv_bfloat16 z = __float2bfloat16(0.f);
#pragma unroll
        for (int jj = 0; jj < JC; jj++) {
            int ci = tid * HH + j0 + jj;
            hb[ci] = z;
            hb[BBHH + ci] = z;
        }
    }
    grid_barrier(e0, 1);

    uint32_t hbA = smem_u32(Hb);
    uint32_t wA[2] = { smem_u32(Whi), smem_u32(Wlo) };

    // ldmatrix address components (R6-proven layout)
    int aRow = (lane & 15);
    int aHalf = (lane >> 4) * 16;
    int gB = lane >> 3;
    int fi01 = (gB >> 1) * 8 + (lane & 7);
    int bHalf01 = (gB & 1) * 16;
    int row2 = 16 + (lane & 7);
    int bHalf2 = ((lane >> 3) & 1) * 16;
    int g4 = lane >> 2, tig = lane & 3;

    const int paA[3] = { 0, 0, 1 };
    const int paW[3] = { 0, 1, 0 };

    // cell-update partition + register-resident cell state
    int eb[3], ejj[3];
    float cr[3] = { 0.f, 0.f, 0.f };
#pragma unroll
    for (int r = 0; r < 3; r++) {
        int e = r * 128 + tid;
        eb[r] = e / JC;
        ejj[r] = e - eb[r] * JC;
    }

    for (int t = 0; t < TT; t++) {
        int pin = t & 1;
        const __nv_bfloat16* hinh = hb + (size_t)(pin * 2 + 0) * BBHH;
        const __nv_bfloat16* hinl = hb + (size_t)(pin * 2 + 1) * BBHH;
        __nv_bfloat16* houth = hb + (size_t)((pin ^ 1) * 2 + 0) * BBHH;
        __nv_bfloat16* houtl = hb + (size_t)((pin ^ 1) * 2 + 1) * BBHH;

        // preamble: issue chunks 0 and 1
        rec_issue(hbA, 0, hinh, hinl, 0, tid);
        rec_issue(hbA, 1, hinh, hinl, KCH, tid);

        // preload pre[t] (and res[t]) into registers; consumed after mma loop.
        float preg[3][4], resv[3];
#pragma unroll
        for (int r = 0; r < 3; r++) {
            int b = eb[r], j = j0 + ejj[r];
            size_t prow = ((size_t)b * TT + t) * GG;
            preg[r][0] = pre[prow + 0*HH + j];
            preg[r][1] = pre[prow + 1*HH + j];
            preg[r][2] = pre[prow + 2*HH + j];
            preg[r][3] = pre[prow + 3*HH + j];
            resv[r] = res ? res[((size_t)b * TT + t) * HH + j] : 0.f;
        }

        float acc[3][4];
#pragma unroll
        for (int f = 0; f < 3; f++)
#pragma unroll
            for (int r = 0; r < 4; r++) acc[f][r] = 0.f;

        for (int c = 0; c < NCHR; c++) {
            int slot = c % 3;
            if (c + 2 < NCHR) {
                rec_issue(hbA, (c + 2) % 3, hinh, hinl, (c + 2) * KCH, tid);
                cpwait<2>();
            } else if (c + 1 < NCHR) {
                cpwait<1>();
            } else {
                cpwait<0>();
            }
            __syncthreads();
            uint32_t Ab[2];
            Ab[0] = hbA + slot * 2 * HTILE2;
            Ab[1] = Ab[0] + HTILE2;
#pragma unroll
            for (int p = 0; p < 3; p++) {
                uint32_t Abase = Ab[paA[p]];
                uint32_t Wbase = wA[paW[p]] + c * 256;   // 128 k = 256 bytes
#pragma unroll
                for (int kk = 0; kk < 8; kk++) {
                    uint32_t a[4];
                    ldsm4(Abase + (w*16 + aRow) * HROW2 + aHalf + kk*32, a);
                    uint32_t b01[4];
                    ldsm4(Wbase + fi01 * WROWB + bHalf01 + kk*32, b01);
                    uint32_t b2[2];
                    ldsm2(Wbase + row2 * WROWB + bHalf2 + kk*32, b2);
                    mma_bf16(acc[0], a, b01[0], b01[1]);
                    mma_bf16(acc[1], a, b01[2], b01[3]);
                    mma_bf16(acc[2], a, b2[0], b2[1]);
                }
            }
            __syncthreads();
        }

        // write gate tile to Csm: row = batch, col = gate*JC + jj
#pragma unroll
        for (int f = 0; f < 3; f++) {
            Csm[(w*16 + g4) * 28 + f*8 + tig*2]     = acc[f][0];
            Csm[(w*16 + g4) * 28 + f*8 + tig*2 + 1] = acc[f][1];
            Csm[(w*16 + 8 + g4) * 28 + f*8 + tig*2]     = acc[f][2];
            Csm[(w*16 + 8 + g4) * 28 + f*8 + tig*2 + 1] = acc[f][3];
        }
        __syncthreads();

        // cell update: 64 b x JC cols = 384 elems, 3 per thread (c in registers)
#pragma unroll
        for (int r = 0; r < 3; r++) {
            int b = eb[r], jj = ejj[r];
            int j = j0 + jj;
            float gi = Csm[b*28 + 0*JC + jj] + preg[r][0];
            float gf = Csm[b*28 + 1*JC + jj] + preg[r][1];
            float gg = Csm[b*28 + 2*JC + jj] + preg[r][2];
            float go = Csm[b*28 + 3*JC + jj] + preg[r][3];
            float si = fsigmoid(gi);
            float sf_ = fsigmoid(gf);
            float so = fsigmoid(go);
            float tg = ftanh(gg);
            float cn = sf_ * cr[r] + si * tg;
            float hn = so * ftanh(cn);
            cr[r] = cn;
            int ci = b * HH + j;
            __nv_bfloat16 hh = __float2bfloat16(hn);
            houth[ci] = hh;
            houtl[ci] = __float2bfloat16(hn - __bfloat162float(hh));
            size_t yi = ((size_t)b * TT + t) * HH + j;
            y[yi] = res ? hn + resv[r] : hn;
        }
        grid_barrier(e0, t + 2);
    }
}

// ---------------- output copy ----------------
__global__ void copy_out(float* __restrict__ out, const float* __restrict__ proj, int n)
{
    int i = blockIdx.x * blockDim.x + threadIdx.x;
    int stride = gridDim.x * blockDim.x;
    for (; i < n; i += stride) {
        int m = i / OUTD, o = i % OUTD;
        out[i] = proj[(size_t)m * 128 + o];
    }
}

// ---------------- driver ----------------
extern "C" void kernel_launch(void* const* d_in, const int* in_sizes, int n_in,
                              void* d_out, int out_size)
{
    const float* x   = (const float*)d_in[0];
    const float* Wih[3] = { (const float*)d_in[1], (const float*)d_in[4], (const float*)d_in[7] };
    const float* Whh[3] = { (const float*)d_in[2], (const float*)d_in[5], (const float*)d_in[8] };
    const float* bgt[3] = { (const float*)d_in[3], (const float*)d_in[6], (const float*)d_in[9] };
    const float* Wp  = (const float*)d_in[10];

    float *pre, *x1, *x2, *x3, *proj;
    __nv_bfloat16 *ah, *al, *bh, *bl, *pph, *ppl, *hbp;
    cudaGetSymbolAddress((void**)&pre,  g_pre);
    cudaGetSymbolAddress((void**)&x1,   g_x1);
    cudaGetSymbolAddress((void**)&x2,   g_x2);
    cudaGetSymbolAddress((void**)&x3,   g_x3);
    cudaGetSymbolAddress((void**)&proj, g_proj);
    cudaGetSymbolAddress((void**)&hbp,  g_hb);
    cudaGetSymbolAddress((void**)&ah,   g_ah);
    cudaGetSymbolAddress((void**)&al,   g_al);
    cudaGetSymbolAddress((void**)&bh,   g_bh);
    cudaGetSymbolAddress((void**)&bl,   g_bl);
    cudaGetSymbolAddress((void**)&pph,  g_ph);
    cudaGetSymbolAddress((void**)&ppl,  g_pl);

    cudaFuncSetAttribute(lstm_persist, cudaFuncAttributeMaxDynamicSharedMemorySize, RSMEM);
    cudaFuncSetAttribute(gemm_mma3, cudaFuncAttributeMaxDynamicSharedMemorySize, GSMEM);

    float* xs[3] = { x1, x2, x3 };
    const float* layerIn = x;
    int K = INF;

    for (int L = 0; L < 3; L++) {
        split_bf16<<<4096, 256>>>(layerIn, ah, al, (size_t)MM * K / 4);
        split_bf16<<<512, 256>>>(Wih[L], bh, bl, (size_t)GG * K / 4);

        dim3 grid(GG / 128, MM / 128);
        gemm_mma3<<<grid, 256, GSMEM>>>(ah, al, bh, bl, bgt[L], pre, K, GG);

        const float* res = (L > 0) ? layerIn : nullptr;
        lstm_persist<<<NCTA, 128, RSMEM>>>(pre, Whh[L], hbp, xs[L], res);

        layerIn = xs[L];
        K = HH;
    }

    // projection
    split_bf16<<<4096, 256>>>(x3, ah, al, (size_t)MM * HH / 4);
    pad_wp_split<<<96, 256>>>(pph, ppl, Wp);
    dim3 gridP(1, MM / 128);
    gemm_mma3<<<gridP, 256, GSMEM>>>(ah, al, pph, ppl, nullptr, proj, HH, 128);
    copy_out<<<1024, 256>>>((float*)d_out, proj, MM * OUTD);
}

// round 10
// speedup vs baseline: 1.9014x; 1.0620x over previous
#include <cuda_runtime.h>
#include <cuda_bf16.h>
#include <math.h>
#include <stdint.h>

#define BB 64
#define TT 1024
#define INF 512
#define HH 768
#define GG 3072          // 4*H
#define MM (BB*TT)       // 65536
#define OUTD 100
#define BBHH (BB*HH)

// recurrence config
#define NCTA 128
#define JC 6             // h columns per CTA
#define NC 24            // gate rows per CTA (4*JC)
#define KCH 128          // k per chunk
#define NCHR 6           // 768/128 chunks (3 per warp-group)
#define WROWB 1552       // W smem row pitch bytes (768*2 + 16)
#define HROW2 272        // h tile row pitch bytes (128*2 + 16)
#define HTILE2 (64*HROW2) // 17408
#define WTILE (NC*WROWB) // 37248
// smem: W(2x) + 4 h slots (2 per group) + 2 Csm regions
#define RSMEM (2*WTILE + 4*(2*HTILE2) + 2*64*28*4)   // 74496+139264+14336=228096? no:
// 4 slots x (hi+lo) = 4*2*HTILE2 = 139264 ; total = 74496+139264+14336 = 228096 > 227? recompute:
// 227 KB limit is 232448. 228096 < 232448. OK.

// GEMM config (fused 4-tile stages, ring-2)
#define HROWB 144        // GEMM tile row pitch (64*2 + 16)
#define GAT (128*HROWB)  // 18432 bytes: one 128x64 bf16 tile
#define GSTAGE (4*GAT)   // Ah, Al, Bh, Bl
#define GSMEM (2*GSTAGE) // 147456

// ---------------- scratch (device globals; no allocation allowed) ----------------
__device__ float g_pre[(size_t)MM * GG];
__device__ float g_x1[(size_t)MM * HH];
__device__ float g_x2[(size_t)MM * HH];
__device__ float g_x3[(size_t)MM * HH];
__device__ float g_proj[(size_t)MM * 128];
__device__ __nv_bfloat16 g_hb[2][2][BBHH];   // [parity][hi/lo]
__device__ unsigned g_count = 0;
__device__ unsigned g_epoch = 0;
// bf16 split buffers
__device__ __nv_bfloat16 g_ah[(size_t)MM * HH];
__device__ __nv_bfloat16 g_al[(size_t)MM * HH];
__device__ __nv_bfloat16 g_bh[(size_t)GG * HH];
__device__ __nv_bfloat16 g_bl[(size_t)GG * HH];
__device__ __nv_bfloat16 g_ph[128 * HH];
__device__ __nv_bfloat16 g_pl[128 * HH];

// ---------------- ptx helpers (base sm_103 ISA only) ----------------
__device__ __forceinline__ void cpasync16(uint32_t saddr, const void* g) {
    asm volatile("cp.async.cg.shared.global [%0], [%1], 16;\n" :: "r"(saddr), "l"(g));
}
__device__ __forceinline__ void cpcommit() { asm volatile("cp.async.commit_group;\n"); }
template<int N> __device__ __forceinline__ void cpwait() {
    asm volatile("cp.async.wait_group %0;\n" :: "n"(N));
}
__device__ __forceinline__ uint32_t smem_u32(const void* p) {
    return (uint32_t)__cvta_generic_to_shared(p);
}
__device__ __forceinline__ void barsync(int id) {
    asm volatile("bar.sync %0, 128;" :: "r"(id) : "memory");
}
__device__ __forceinline__ void ldsm4(uint32_t addr, uint32_t* r) {
    asm volatile("ldmatrix.sync.aligned.m8n8.x4.shared.b16 {%0,%1,%2,%3}, [%4];"
                 : "=r"(r[0]), "=r"(r[1]), "=r"(r[2]), "=r"(r[3]) : "r"(addr));
}
__device__ __forceinline__ void ldsm2(uint32_t addr, uint32_t* r) {
    asm volatile("ldmatrix.sync.aligned.m8n8.x2.shared.b16 {%0,%1}, [%2];"
                 : "=r"(r[0]), "=r"(r[1]) : "r"(addr));
}
__device__ __forceinline__ void mma_bf16(float* d, const uint32_t* a, uint32_t b0, uint32_t b1) {
    asm volatile(
        "mma.sync.aligned.m16n8k16.row.col.f32.bf16.bf16.f32 "
        "{%0,%1,%2,%3}, {%4,%5,%6,%7}, {%8,%9}, {%0,%1,%2,%3};"
        : "+f"(d[0]), "+f"(d[1]), "+f"(d[2]), "+f"(d[3])
        : "r"(a[0]), "r"(a[1]), "r"(a[2]), "r"(a[3]), "r"(b0), "r"(b1));
}

// fast sigmoid / tanh (clamped, no-NaN; err ~1e-6)
__device__ __forceinline__ float fsigmoid(float x) {
    return __fdividef(1.f, 1.f + __expf(-x));
}
__device__ __forceinline__ float ftanh(float x) {
    x = fminf(15.f, fmaxf(-15.f, x));
    float e2 = __expf(2.f * x);
    return __fdividef(e2 - 1.f, e2 + 1.f);
}

// ---------------- software grid barrier (proven atomic version) ----------------
__device__ __forceinline__ void grid_barrier(unsigned e0, unsigned target) {
    __threadfence();
    __syncthreads();
    if (threadIdx.x == 0) {
        unsigned a = atomicAdd(&g_count, 1);
        if (a == NCTA - 1) {
            g_count = 0;
            __threadfence();
            atomicAdd(&g_epoch, 1);
        } else {
            while ((*(volatile unsigned*)&g_epoch) - e0 < target) { }
            __threadfence();
        }
    }
    __syncthreads();
}

// ---------------- bf16 split conversions ----------------
__global__ void split_bf16(const float* __restrict__ src,
                           __nv_bfloat16* __restrict__ hi,
                           __nv_bfloat16* __restrict__ lo, size_t n4)
{
    size_t i = (size_t)blockIdx.x * blockDim.x + threadIdx.x;
    size_t stride = (size_t)gridDim.x * blockDim.x;
    for (; i < n4; i += stride) {
        float4 v = ((const float4*)src)[i];
        __nv_bfloat16 h0 = __float2bfloat16(v.x);
        __nv_bfloat16 h1 = __float2bfloat16(v.y);
        __nv_bfloat16 h2 = __float2bfloat16(v.z);
        __nv_bfloat16 h3 = __float2bfloat16(v.w);
        __nv_bfloat162 hp0; hp0.x = h0; hp0.y = h1;
        __nv_bfloat162 hp1; hp1.x = h2; hp1.y = h3;
        __nv_bfloat162 lp0;
        lp0.x = __float2bfloat16(v.x - __bfloat162float(h0));
        lp0.y = __float2bfloat16(v.y - __bfloat162float(h1));
        __nv_bfloat162 lp1;
        lp1.x = __float2bfloat16(v.z - __bfloat162float(h2));
        lp1.y = __float2bfloat16(v.w - __bfloat162float(h3));
        ((__nv_bfloat162*)hi)[2*i]   = hp0;
        ((__nv_bfloat162*)hi)[2*i+1] = hp1;
        ((__nv_bfloat162*)lo)[2*i]   = lp0;
        ((__nv_bfloat162*)lo)[2*i+1] = lp1;
    }
}

__global__ void pad_wp_split(__nv_bfloat16* __restrict__ ph,
                             __nv_bfloat16* __restrict__ pl,
                             const float* __restrict__ Wp)
{
    int i = blockIdx.x * blockDim.x + threadIdx.x;
    int stride = gridDim.x * blockDim.x;
    for (; i < 128 * HH; i += stride) {
        int o = i / HH, k = i % HH;
        float v = (o < OUTD) ? Wp[o * HH + k] : 0.f;
        __nv_bfloat16 h = __float2bfloat16(v);
        ph[i] = h;
        pl[i] = __float2bfloat16(v - __bfloat162float(h));
    }
}

// ---------------- bf16x3 GEMM, fused passes, ring-2 ----------------
__device__ __forceinline__ void gemm_issue4(uint32_t sb, int stage,
                                            const __nv_bfloat16* Ah, const __nv_bfloat16* Al,
                                            const __nv_bfloat16* Bh, const __nv_bfloat16* Bl,
                                            int m0, int n0, int K, int ck, int tid)
{
    uint32_t base = sb + stage * GSTAGE;
    const __nv_bfloat16* srcs[4] = {
        Ah + (size_t)m0 * K + ck, Al + (size_t)m0 * K + ck,
        Bh + (size_t)n0 * K + ck, Bl + (size_t)n0 * K + ck };
#pragma unroll
    for (int tile = 0; tile < 4; tile++) {
        uint32_t dst = base + tile * GAT;
        const __nv_bfloat16* src = srcs[tile];
#pragma unroll
        for (int it = 0; it < 4; it++) {
            int idx = it * 256 + tid;
            int row = idx >> 3, seg = idx & 7;
            cpasync16(dst + row * HROWB + seg * 16, src + (size_t)row * K + seg * 8);
        }
    }
    cpcommit();
}

__global__ __launch_bounds__(256)
void gemm_mma3(const __nv_bfloat16* __restrict__ Ah, const __nv_bfloat16* __restrict__ Al,
               const __nv_bfloat16* __restrict__ Bh, const __nv_bfloat16* __restrict__ Bl,
               const float* __restrict__ bias, float* __restrict__ C,
               int K, int Ntot)
{
    extern __shared__ __align__(128) char gsm[];
    uint32_t sb = smem_u32(gsm);

    int tid = threadIdx.x;
    int lane = tid & 31;
    int wid = tid >> 5;
    int wm = wid & 3;
    int wn = wid >> 2;
    int m0 = blockIdx.y * 128;
    int n0 = blockIdx.x * 128;

    const int cps = K >> 6;

    float acc[2][8][4];
#pragma unroll
    for (int mt = 0; mt < 2; mt++)
#pragma unroll
        for (int f = 0; f < 8; f++)
#pragma unroll
            for (int r = 0; r < 4; r++) acc[mt][f][r] = 0.f;

    int aRow = (lane & 15);
    int aHalf = (lane >> 4) * 16;
    int gB = lane >> 3;
    int bHalf = (gB & 1) * 16;

    gemm_issue4(sb, 0, Ah, Al, Bh, Bl, m0, n0, K, 0, tid);
    if (cps > 1) gemm_issue4(sb, 1, Ah, Al, Bh, Bl, m0, n0, K, 64, tid);

    for (int c = 0; c < cps; c++) {
        int stage = c & 1;
        if (c + 1 < cps) cpwait<1>(); else cpwait<0>();
        __syncthreads();
        uint32_t tAh = sb + stage * GSTAGE;
        uint32_t tAl = tAh + GAT;
        uint32_t tBh = tAh + 2 * GAT;
        uint32_t tBl = tAh + 3 * GAT;
#pragma unroll
        for (int kk = 0; kk < 4; kk++) {
            uint32_t ah[2][4], al[2][4];
#pragma unroll
            for (int mt = 0; mt < 2; mt++) {
                ldsm4(tAh + (wm*32 + mt*16 + aRow) * HROWB + aHalf + kk*32, ah[mt]);
                ldsm4(tAl + (wm*32 + mt*16 + aRow) * HROWB + aHalf + kk*32, al[mt]);
            }
            uint32_t bh[8][2], bl[8][2];
#pragma unroll
            for (int fp = 0; fp < 4; fp++) {
                int fi = fp * 2 + (gB >> 1);
                uint32_t roff = (wn*64 + fi*8 + (lane & 7)) * HROWB + bHalf + kk*32;
                uint32_t r4[4];
                ldsm4(tBh + roff, r4);
                bh[fp*2][0]   = r4[0]; bh[fp*2][1]   = r4[1];
                bh[fp*2+1][0] = r4[2]; bh[fp*2+1][1] = r4[3];
                ldsm4(tBl + roff, r4);
                bl[fp*2][0]   = r4[0]; bl[fp*2][1]   = r4[1];
                bl[fp*2+1][0] = r4[2]; bl[fp*2+1][1] = r4[3];
            }
#pragma unroll
            for (int mt = 0; mt < 2; mt++)
#pragma unroll
                for (int f = 0; f < 8; f++) {
                    mma_bf16(acc[mt][f], ah[mt], bh[f][0], bh[f][1]);
                    mma_bf16(acc[mt][f], ah[mt], bl[f][0], bl[f][1]);
                    mma_bf16(acc[mt][f], al[mt], bh[f][0], bh[f][1]);
                }
        }
        __syncthreads();
        if (c + 2 < cps)
            gemm_issue4(sb, stage, Ah, Al, Bh, Bl, m0, n0, K, (c + 2) * 64, tid);
    }

    int g4 = lane >> 2, tig = lane & 3;
#pragma unroll
    for (int mt = 0; mt < 2; mt++) {
#pragma unroll
        for (int f = 0; f < 8; f++) {
            int r0 = m0 + wm*32 + mt*16 + g4;
            int c0 = n0 + wn*64 + f*8 + tig*2;
            float b0 = bias ? bias[c0] : 0.f;
            float b1 = bias ? bias[c0+1] : 0.f;
            float2 v0; v0.x = acc[mt][f][0] + b0; v0.y = acc[mt][f][1] + b1;
            float2 v1; v1.x = acc[mt][f][2] + b0; v1.y = acc[mt][f][3] + b1;
            *(float2*)&C[(size_t)r0 * Ntot + c0] = v0;
            *(float2*)&C[(size_t)(r0 + 8) * Ntot + c0] = v1;
        }
    }
}

// ---------------- persistent LSTM: 256 threads, split-K warp groups ----------------
// Group gid (warps gid*4..gid*4+3) handles k-chunks gid*3..gid*3+2 with its own
// 2-slot ring and named barrier (id 1+gid). Partial gates in Csm[gid].
__device__ __forceinline__ void rec_issue(uint32_t hbA, int slot,
                                          const __nv_bfloat16* hhi,
                                          const __nv_bfloat16* hlo,
                                          int k0, int ltid)
{
    uint32_t dH = hbA + slot * 2 * HTILE2;
    uint32_t dL = dH + HTILE2;
#pragma unroll
    for (int it = 0; it < 8; it++) {
        int idx = it * 128 + ltid;        // 1024 granules per matrix, 128 threads
        int row = idx >> 4, seg = idx & 15;
        cpasync16(dH + row * HROW2 + seg * 16, hhi + (size_t)row * HH + k0 + seg * 8);
        cpasync16(dL + row * HROW2 + seg * 16, hlo + (size_t)row * HH + k0 + seg * 8);
    }
    cpcommit();
}

__global__ __launch_bounds__(256, 1)
void lstm_persist(const float* __restrict__ pre, const float* __restrict__ Whh,
                  __nv_bfloat16* __restrict__ hb,
                  float* __restrict__ y, const float* __restrict__ res)
{
    extern __shared__ __align__(128) char rsm[];
    char* Whi = rsm;
    char* Wlo = rsm + WTILE;
    char* Hb  = rsm + 2 * WTILE;                        // 4 slots x (hi+lo)
    float* Csm0 = (float*)(rsm + 2 * WTILE + 4 * (2 * HTILE2));
    float* Csm1 = Csm0 + 64 * 28;

    int tid = threadIdx.x;
    int lane = tid & 31;
    int wid = tid >> 5;
    int gid = wid >> 2;          // warp group 0/1
    int w = wid & 3;             // row group within warp group
    int ltid = tid & 127;        // thread id within group
    int j0 = blockIdx.x * JC;
    unsigned e0 = 0;
    if (tid == 0) e0 = *(volatile unsigned*)&g_epoch;

    float* CsmMy = gid ? Csm1 : Csm0;

    // cache Whh slice as bf16 hi/lo. SMEM row r = gate r/JC, col j0 + r%JC.
    for (int i = tid; i < NC * HH; i += 256) {
        int r = i / HH, k = i - r * HH;
        int g = r / JC, jj = r - g * JC;
        float v = Whh[(size_t)(g * HH + j0 + jj) * HH + k];
        __nv_bfloat16 h = __float2bfloat16(v);
        ((__nv_bfloat16*)(Whi + r * WROWB))[k] = h;
        ((__nv_bfloat16*)(Wlo + r * WROWB))[k] = __float2bfloat16(v - __bfloat162float(h));
    }

    // zero h (parity 0, hi+lo) for owned columns
    if (tid < BB) {
        __nv_bfloat16 z = __float2bfloat16(0.f);
#pragma unroll
        for (int jj = 0; jj < JC; jj++) {
            int ci = tid * HH + j0 + jj;
            hb[ci] = z;
            hb[BBHH + ci] = z;
        }
    }
    grid_barrier(e0, 1);

    uint32_t hbA = smem_u32(Hb);
    uint32_t wA[2] = { smem_u32(Whi), smem_u32(Wlo) };

    // ldmatrix address components (proven layout)
    int aRow = (lane & 15);
    int aHalf = (lane >> 4) * 16;
    int gB = lane >> 3;
    int fi01 = (gB >> 1) * 8 + (lane & 7);
    int bHalf01 = (gB & 1) * 16;
    int row2 = 16 + (lane & 7);
    int bHalf2 = ((lane >> 3) & 1) * 16;
    int g4 = lane >> 2, tig = lane & 3;

    const int paA[3] = { 0, 0, 1 };
    const int paW[3] = { 0, 1, 0 };

    // cell-update partition: elem e0c = tid (always), e1c = 256+tid (tid<128)
    int b0c = tid / JC, j0c = tid - b0c * JC;
    int b1c = (256 + tid) / JC, j1c = (256 + tid) - b1c * JC;
    bool has2 = (tid < 128);
    float cr0 = 0.f, cr1 = 0.f;

    for (int t = 0; t < TT; t++) {
        int pin = t & 1;
        const __nv_bfloat16* hinh = hb + (size_t)(pin * 2 + 0) * BBHH;
        const __nv_bfloat16* hinl = hb + (size_t)(pin * 2 + 1) * BBHH;
        __nv_bfloat16* houth = hb + (size_t)((pin ^ 1) * 2 + 0) * BBHH;
        __nv_bfloat16* houtl = hb + (size_t)((pin ^ 1) * 2 + 1) * BBHH;

        // group preamble: issue chunks gid*3, gid*3+1 into slots gid*2, gid*2+1
        rec_issue(hbA, gid * 2 + 0, hinh, hinl, (gid * 3 + 0) * KCH, ltid);
        rec_issue(hbA, gid * 2 + 1, hinh, hinl, (gid * 3 + 1) * KCH, ltid);

        // preload pre[t] / res[t] into registers
        float pr0[4], pr1[4], rv0 = 0.f, rv1 = 0.f;
        {
            int jj = j0 + j0c;
            size_t prow = ((size_t)b0c * TT + t) * GG;
            pr0[0] = pre[prow + 0*HH + jj];
            pr0[1] = pre[prow + 1*HH + jj];
            pr0[2] = pre[prow + 2*HH + jj];
            pr0[3] = pre[prow + 3*HH + jj];
            if (res) rv0 = res[((size_t)b0c * TT + t) * HH + jj];
        }
        if (has2) {
            int jj = j0 + j1c;
            size_t prow = ((size_t)b1c * TT + t) * GG;
            pr1[0] = pre[prow + 0*HH + jj];
            pr1[1] = pre[prow + 1*HH + jj];
            pr1[2] = pre[prow + 2*HH + jj];
            pr1[3] = pre[prow + 3*HH + jj];
            if (res) rv1 = res[((size_t)b1c * TT + t) * HH + jj];
        }

        float acc[3][4];
#pragma unroll
        for (int f = 0; f < 3; f++)
#pragma unroll
            for (int r = 0; r < 4; r++) acc[f][r] = 0.f;

        // group-local chunk loop: 3 chunks, 2-slot ring
#pragma unroll
        for (int i = 0; i < 3; i++) {
            int c = gid * 3 + i;
            int slot = gid * 2 + (i & 1);
            if (i == 2) cpwait<0>(); else cpwait<1>();
            barsync(1 + gid);
            uint32_t Ab[2];
            Ab[0] = hbA + slot * 2 * HTILE2;
            Ab[1] = Ab[0] + HTILE2;
#pragma unroll
            for (int p = 0; p < 3; p++) {
                uint32_t Abase = Ab[paA[p]];
                uint32_t Wbase = wA[paW[p]] + c * 256;   // 128 k = 256 bytes
#pragma unroll
                for (int kk = 0; kk < 8; kk++) {
                    uint32_t a[4];
                    ldsm4(Abase + (w*16 + aRow) * HROW2 + aHalf + kk*32, a);
                    uint32_t b01[4];
                    ldsm4(Wbase + fi01 * WROWB + bHalf01 + kk*32, b01);
                    uint32_t b2[2];
                    ldsm2(Wbase + row2 * WROWB + bHalf2 + kk*32, b2);
                    mma_bf16(acc[0], a, b01[0], b01[1]);
                    mma_bf16(acc[1], a, b01[2], b01[3]);
                    mma_bf16(acc[2], a, b2[0], b2[1]);
                }
            }
            barsync(1 + gid);
            if (i == 0)
                rec_issue(hbA, slot, hinh, hinl, (gid * 3 + 2) * KCH, ltid);
        }

        // write partial gate tile to this group's Csm region
#pragma unroll
        for (int f = 0; f < 3; f++) {
            CsmMy[(w*16 + g4) * 28 + f*8 + tig*2]     = acc[f][0];
            CsmMy[(w*16 + g4) * 28 + f*8 + tig*2 + 1] = acc[f][1];
            CsmMy[(w*16 + 8 + g4) * 28 + f*8 + tig*2]     = acc[f][2];
            CsmMy[(w*16 + 8 + g4) * 28 + f*8 + tig*2 + 1] = acc[f][3];
        }
        __syncthreads();

        // cell update: 384 elems over 256 threads (1-2 each), c in registers
        {
            int b = b0c, jj = j0c, j = j0 + jj;
            float gi = Csm0[b*28 + 0*JC + jj] + Csm1[b*28 + 0*JC + jj] + pr0[0];
            float gf = Csm0[b*28 + 1*JC + jj] + Csm1[b*28 + 1*JC + jj] + pr0[1];
            float gg = Csm0[b*28 + 2*JC + jj] + Csm1[b*28 + 2*JC + jj] + pr0[2];
            float go = Csm0[b*28 + 3*JC + jj] + Csm1[b*28 + 3*JC + jj] + pr0[3];
            float si = fsigmoid(gi), sf_ = fsigmoid(gf), so = fsigmoid(go);
            float tg = ftanh(gg);
            float cn = sf_ * cr0 + si * tg;
            float hn = so * ftanh(cn);
            cr0 = cn;
            int ci = b * HH + j;
            __nv_bfloat16 hh = __float2bfloat16(hn);
            houth[ci] = hh;
            houtl[ci] = __float2bfloat16(hn - __bfloat162float(hh));
            y[((size_t)b * TT + t) * HH + j] = res ? hn + rv0 : hn;
        }
        if (has2) {
            int b = b1c, jj = j1c, j = j0 + jj;
            float gi = Csm0[b*28 + 0*JC + jj] + Csm1[b*28 + 0*JC + jj] + pr1[0];
            float gf = Csm0[b*28 + 1*JC + jj] + Csm1[b*28 + 1*JC + jj] + pr1[1];
            float gg = Csm0[b*28 + 2*JC + jj] + Csm1[b*28 + 2*JC + jj] + pr1[2];
            float go = Csm0[b*28 + 3*JC + jj] + Csm1[b*28 + 3*JC + jj] + pr1[3];
            float si = fsigmoid(gi), sf_ = fsigmoid(gf), so = fsigmoid(go);
            float tg = ftanh(gg);
            float cn = sf_ * cr1 + si * tg;
            float hn = so * ftanh(cn);
            cr1 = cn;
            int ci = b * HH + j;
            __nv_bfloat16 hh = __float2bfloat16(hn);
            houth[ci] = hh;
            houtl[ci] = __float2bfloat16(hn - __bfloat162float(hh));
            y[((size_t)b * TT + t) * HH + j] = res ? hn + rv1 : hn;
        }
        grid_barrier(e0, t + 2);
    }
}

// ---------------- output copy ----------------
__global__ void copy_out(float* __restrict__ out, const float* __restrict__ proj, int n)
{
    int i = blockIdx.x * blockDim.x + threadIdx.x;
    int stride = gridDim.x * blockDim.x;
    for (; i < n; i += stride) {
        int m = i / OUTD, o = i % OUTD;
        out[i] = proj[(size_t)m * 128 + o];
    }
}

// ---------------- driver ----------------
extern "C" void kernel_launch(void* const* d_in, const int* in_sizes, int n_in,
                              void* d_out, int out_size)
{
    const float* x   = (const float*)d_in[0];
    const float* Wih[3] = { (const float*)d_in[1], (const float*)d_in[4], (const float*)d_in[7] };
    const float* Whh[3] = { (const float*)d_in[2], (const float*)d_in[5], (const float*)d_in[8] };
    const float* bgt[3] = { (const float*)d_in[3], (const float*)d_in[6], (const float*)d_in[9] };
    const float* Wp  = (const float*)d_in[10];

    float *pre, *x1, *x2, *x3, *proj;
    __nv_bfloat16 *ah, *al, *bh, *bl, *pph, *ppl, *hbp;
    cudaGetSymbolAddress((void**)&pre,  g_pre);
    cudaGetSymbolAddress((void**)&x1,   g_x1);
    cudaGetSymbolAddress((void**)&x2,   g_x2);
    cudaGetSymbolAddress((void**)&x3,   g_x3);
    cudaGetSymbolAddress((void**)&proj, g_proj);
    cudaGetSymbolAddress((void**)&hbp,  g_hb);
    cudaGetSymbolAddress((void**)&ah,   g_ah);
    cudaGetSymbolAddress((void**)&al,   g_al);
    cudaGetSymbolAddress((void**)&bh,   g_bh);
    cudaGetSymbolAddress((void**)&bl,   g_bl);
    cudaGetSymbolAddress((void**)&pph,  g_ph);
    cudaGetSymbolAddress((void**)&ppl,  g_pl);

    const int RS = 2*WTILE + 4*(2*HTILE2) + 2*64*28*4;
    cudaFuncSetAttribute(lstm_persist, cudaFuncAttributeMaxDynamicSharedMemorySize, RS);
    cudaFuncSetAttribute(gemm_mma3, cudaFuncAttributeMaxDynamicSharedMemorySize, GSMEM);

    float* xs[3] = { x1, x2, x3 };
    const float* layerIn = x;
    int K = INF;

    for (int L = 0; L < 3; L++) {
        split_bf16<<<4096, 256>>>(layerIn, ah, al, (size_t)MM * K / 4);
        split_bf16<<<512, 256>>>(Wih[L], bh, bl, (size_t)GG * K / 4);

        dim3 grid(GG / 128, MM / 128);
        gemm_mma3<<<grid, 256, GSMEM>>>(ah, al, bh, bl, bgt[L], pre, K, GG);

        const float* res = (L > 0) ? layerIn : nullptr;
        lstm_persist<<<NCTA, 256, RS>>>(pre, Whh[L], hbp, xs[L], res);

        layerIn = xs[L];
        K = HH;
    }

    // projection
    split_bf16<<<4096, 256>>>(x3, ah, al, (size_t)MM * HH / 4);
    pad_wp_split<<<96, 256>>>(pph, ppl, Wp);
    dim3 gridP(1, MM / 128);
    gemm_mma3<<<gridP, 256, GSMEM>>>(ah, al, pph, ppl, nullptr, proj, HH, 128);
    copy_out<<<1024, 256>>>((float*)d_out, proj, MM * OUTD);
}

// round 11
// speedup vs baseline: 2.1605x; 1.1363x over previous
#include <cuda_runtime.h>
#include <cuda_bf16.h>
#include <math.h>
#include <stdint.h>

#define BB 64
#define TT 1024
#define INF 512
#define HH 768
#define GG 3072          // 4*H
#define MM (BB*TT)       // 65536
#define OUTD 100
#define BBHH (BB*HH)

// recurrence config
#define NCTA 128
#define JC 6             // h columns per CTA
#define NC 24            // gate rows per CTA (4*JC)
#define KCH 128          // k per chunk
#define WROWB 1552       // W smem row pitch bytes (768*2 + 16)
#define HROW2 272        // h tile row pitch bytes (128*2 + 16)
#define HTILE2 (64*HROW2) // 17408
#define WTILE (NC*WROWB) // 37248
// smem: W(hi+lo) + 4 h slots (hi only; 2 per group) + 2 Csm regions
#define RSMEM (2*WTILE + 4*HTILE2 + 2*64*28*4)   // 74496+69632+14336 = 158464

// GEMM config (fused 4-tile stages, ring-2)
#define HROWB 144        // GEMM tile row pitch (64*2 + 16)
#define GAT (128*HROWB)  // 18432 bytes: one 128x64 bf16 tile
#define GSTAGE (4*GAT)   // Ah, Al, Bh, Bl
#define GSMEM (2*GSTAGE) // 147456

// ---------------- scratch (device globals; no allocation allowed) ----------------
__device__ float g_pre[(size_t)MM * GG];
__device__ float g_x1[(size_t)MM * HH];
__device__ float g_x2[(size_t)MM * HH];
__device__ float g_x3[(size_t)MM * HH];
__device__ float g_proj[(size_t)MM * 128];
__device__ __nv_bfloat16 g_hb[2][BBHH];      // [parity] hi only
__device__ unsigned g_count = 0;
__device__ unsigned g_epoch = 0;
// bf16 split buffers
__device__ __nv_bfloat16 g_ah[(size_t)MM * HH];
__device__ __nv_bfloat16 g_al[(size_t)MM * HH];
__device__ __nv_bfloat16 g_bh[(size_t)GG * HH];
__device__ __nv_bfloat16 g_bl[(size_t)GG * HH];
__device__ __nv_bfloat16 g_ph[128 * HH];
__device__ __nv_bfloat16 g_pl[128 * HH];

// ---------------- ptx helpers (base sm_103 ISA only) ----------------
__device__ __forceinline__ void cpasync16(uint32_t saddr, const void* g) {
    asm volatile("cp.async.cg.shared.global [%0], [%1], 16;\n" :: "r"(saddr), "l"(g));
}
__device__ __forceinline__ void cpcommit() { asm volatile("cp.async.commit_group;\n"); }
template<int N> __device__ __forceinline__ void cpwait() {
    asm volatile("cp.async.wait_group %0;\n" :: "n"(N));
}
__device__ __forceinline__ uint32_t smem_u32(const void* p) {
    return (uint32_t)__cvta_generic_to_shared(p);
}
__device__ __forceinline__ void barsync(int id) {
    asm volatile("bar.sync %0, 128;" :: "r"(id) : "memory");
}
__device__ __forceinline__ void ldsm4(uint32_t addr, uint32_t* r) {
    asm volatile("ldmatrix.sync.aligned.m8n8.x4.shared.b16 {%0,%1,%2,%3}, [%4];"
                 : "=r"(r[0]), "=r"(r[1]), "=r"(r[2]), "=r"(r[3]) : "r"(addr));
}
__device__ __forceinline__ void ldsm2(uint32_t addr, uint32_t* r) {
    asm volatile("ldmatrix.sync.aligned.m8n8.x2.shared.b16 {%0,%1}, [%2];"
                 : "=r"(r[0]), "=r"(r[1]) : "r"(addr));
}
__device__ __forceinline__ void mma_bf16(float* d, const uint32_t* a, uint32_t b0, uint32_t b1) {
    asm volatile(
        "mma.sync.aligned.m16n8k16.row.col.f32.bf16.bf16.f32 "
        "{%0,%1,%2,%3}, {%4,%5,%6,%7}, {%8,%9}, {%0,%1,%2,%3};"
        : "+f"(d[0]), "+f"(d[1]), "+f"(d[2]), "+f"(d[3])
        : "r"(a[0]), "r"(a[1]), "r"(a[2]), "r"(a[3]), "r"(b0), "r"(b1));
}

// fast sigmoid / tanh (clamped, no-NaN; err ~1e-6)
__device__ __forceinline__ float fsigmoid(float x) {
    return __fdividef(1.f, 1.f + __expf(-x));
}
__device__ __forceinline__ float ftanh(float x) {
    x = fminf(15.f, fmaxf(-15.f, x));
    float e2 = __expf(2.f * x);
    return __fdividef(e2 - 1.f, e2 + 1.f);
}

// ---------------- software grid barrier (proven atomic version) ----------------
__device__ __forceinline__ void grid_barrier(unsigned e0, unsigned target) {
    __threadfence();
    __syncthreads();
    if (threadIdx.x == 0) {
        unsigned a = atomicAdd(&g_count, 1);
        if (a == NCTA - 1) {
            g_count = 0;
            __threadfence();
            atomicAdd(&g_epoch, 1);
        } else {
            while ((*(volatile unsigned*)&g_epoch) - e0 < target) { }
            __threadfence();
        }
    }
    __syncthreads();
}

// ---------------- bf16 split conversions ----------------
__global__ void split_bf16(const float* __restrict__ src,
                           __nv_bfloat16* __restrict__ hi,
                           __nv_bfloat16* __restrict__ lo, size_t n4)
{
    size_t i = (size_t)blockIdx.x * blockDim.x + threadIdx.x;
    size_t stride = (size_t)gridDim.x * blockDim.x;
    for (; i < n4; i += stride) {
        float4 v = ((const float4*)src)[i];
        __nv_bfloat16 h0 = __float2bfloat16(v.x);
        __nv_bfloat16 h1 = __float2bfloat16(v.y);
        __nv_bfloat16 h2 = __float2bfloat16(v.z);
        __nv_bfloat16 h3 = __float2bfloat16(v.w);
        __nv_bfloat162 hp0; hp0.x = h0; hp0.y = h1;
        __nv_bfloat162 hp1; hp1.x = h2; hp1.y = h3;
        __nv_bfloat162 lp0;
        lp0.x = __float2bfloat16(v.x - __bfloat162float(h0));
        lp0.y = __float2bfloat16(v.y - __bfloat162float(h1));
        __nv_bfloat162 lp1;
        lp1.x = __float2bfloat16(v.z - __bfloat162float(h2));
        lp1.y = __float2bfloat16(v.w - __bfloat162float(h3));
        ((__nv_bfloat162*)hi)[2*i]   = hp0;
        ((__nv_bfloat162*)hi)[2*i+1] = hp1;
        ((__nv_bfloat162*)lo)[2*i]   = lp0;
        ((__nv_bfloat162*)lo)[2*i+1] = lp1;
    }
}

__global__ void pad_wp_split(__nv_bfloat16* __restrict__ ph,
                             __nv_bfloat16* __restrict__ pl,
                             const float* __restrict__ Wp)
{
    int i = blockIdx.x * blockDim.x + threadIdx.x;
    int stride = gridDim.x * blockDim.x;
    for (; i < 128 * HH; i += stride) {
        int o = i / HH, k = i % HH;
        float v = (o < OUTD) ? Wp[o * HH + k] : 0.f;
        __nv_bfloat16 h = __float2bfloat16(v);
        ph[i] = h;
        pl[i] = __float2bfloat16(v - __bfloat162float(h));
    }
}

// ---------------- bf16x3 GEMM, fused passes, ring-2 (R10-proven) ----------------
__device__ __forceinline__ void gemm_issue4(uint32_t sb, int stage,
                                            const __nv_bfloat16* Ah, const __nv_bfloat16* Al,
                                            const __nv_bfloat16* Bh, const __nv_bfloat16* Bl,
                                            int m0, int n0, int K, int ck, int tid)
{
    uint32_t base = sb + stage * GSTAGE;
    const __nv_bfloat16* srcs[4] = {
        Ah + (size_t)m0 * K + ck, Al + (size_t)m0 * K + ck,
        Bh + (size_t)n0 * K + ck, Bl + (size_t)n0 * K + ck };
#pragma unroll
    for (int tile = 0; tile < 4; tile++) {
        uint32_t dst = base + tile * GAT;
        const __nv_bfloat16* src = srcs[tile];
#pragma unroll
        for (int it = 0; it < 4; it++) {
            int idx = it * 256 + tid;
            int row = idx >> 3, seg = idx & 7;
            cpasync16(dst + row * HROWB + seg * 16, src + (size_t)row * K + seg * 8);
        }
    }
    cpcommit();
}

__global__ __launch_bounds__(256)
void gemm_mma3(const __nv_bfloat16* __restrict__ Ah, const __nv_bfloat16* __restrict__ Al,
               const __nv_bfloat16* __restrict__ Bh, const __nv_bfloat16* __restrict__ Bl,
               const float* __restrict__ bias, float* __restrict__ C,
               int K, int Ntot)
{
    extern __shared__ __align__(128) char gsm[];
    uint32_t sb = smem_u32(gsm);

    int tid = threadIdx.x;
    int lane = tid & 31;
    int wid = tid >> 5;
    int wm = wid & 3;
    int wn = wid >> 2;
    int m0 = blockIdx.y * 128;
    int n0 = blockIdx.x * 128;

    const int cps = K >> 6;

    float acc[2][8][4];
#pragma unroll
    for (int mt = 0; mt < 2; mt++)
#pragma unroll
        for (int f = 0; f < 8; f++)
#pragma unroll
            for (int r = 0; r < 4; r++) acc[mt][f][r] = 0.f;

    int aRow = (lane & 15);
    int aHalf = (lane >> 4) * 16;
    int gB = lane >> 3;
    int bHalf = (gB & 1) * 16;

    gemm_issue4(sb, 0, Ah, Al, Bh, Bl, m0, n0, K, 0, tid);
    if (cps > 1) gemm_issue4(sb, 1, Ah, Al, Bh, Bl, m0, n0, K, 64, tid);

    for (int c = 0; c < cps; c++) {
        int stage = c & 1;
        if (c + 1 < cps) cpwait<1>(); else cpwait<0>();
        __syncthreads();
        uint32_t tAh = sb + stage * GSTAGE;
        uint32_t tAl = tAh + GAT;
        uint32_t tBh = tAh + 2 * GAT;
        uint32_t tBl = tAh + 3 * GAT;
#pragma unroll
        for (int kk = 0; kk < 4; kk++) {
            uint32_t ah[2][4], al[2][4];
#pragma unroll
            for (int mt = 0; mt < 2; mt++) {
                ldsm4(tAh + (wm*32 + mt*16 + aRow) * HROWB + aHalf + kk*32, ah[mt]);
                ldsm4(tAl + (wm*32 + mt*16 + aRow) * HROWB + aHalf + kk*32, al[mt]);
            }
            uint32_t bh[8][2], bl[8][2];
#pragma unroll
            for (int fp = 0; fp < 4; fp++) {
                int fi = fp * 2 + (gB >> 1);
                uint32_t roff = (wn*64 + fi*8 + (lane & 7)) * HROWB + bHalf + kk*32;
                uint32_t r4[4];
                ldsm4(tBh + roff, r4);
                bh[fp*2][0]   = r4[0]; bh[fp*2][1]   = r4[1];
                bh[fp*2+1][0] = r4[2]; bh[fp*2+1][1] = r4[3];
                ldsm4(tBl + roff, r4);
                bl[fp*2][0]   = r4[0]; bl[fp*2][1]   = r4[1];
                bl[fp*2+1][0] = r4[2]; bl[fp*2+1][1] = r4[3];
            }
#pragma unroll
            for (int mt = 0; mt < 2; mt++)
#pragma unroll
                for (int f = 0; f < 8; f++) {
                    mma_bf16(acc[mt][f], ah[mt], bh[f][0], bh[f][1]);
                    mma_bf16(acc[mt][f], ah[mt], bl[f][0], bl[f][1]);
                    mma_bf16(acc[mt][f], al[mt], bh[f][0], bh[f][1]);
                }
        }
        __syncthreads();
        if (c + 2 < cps)
            gemm_issue4(sb, stage, Ah, Al, Bh, Bl, m0, n0, K, (c + 2) * 64, tid);
    }

    int g4 = lane >> 2, tig = lane & 3;
#pragma unroll
    for (int mt = 0; mt < 2; mt++) {
#pragma unroll
        for (int f = 0; f < 8; f++) {
            int r0 = m0 + wm*32 + mt*16 + g4;
            int c0 = n0 + wn*64 + f*8 + tig*2;
            float b0 = bias ? bias[c0] : 0.f;
            float b1 = bias ? bias[c0+1] : 0.f;
            float2 v0; v0.x = acc[mt][f][0] + b0; v0.y = acc[mt][f][1] + b1;
            float2 v1; v1.x = acc[mt][f][2] + b0; v1.y = acc[mt][f][3] + b1;
            *(float2*)&C[(size_t)r0 * Ntot + c0] = v0;
            *(float2*)&C[(size_t)(r0 + 8) * Ntot + c0] = v1;
        }
    }
}

// ---------------- persistent LSTM: 256 threads, split-K, h hi-only ----------------
__device__ __forceinline__ void rec_issue(uint32_t hbA, int slot,
                                          const __nv_bfloat16* hhi,
                                          int k0, int ltid)
{
    uint32_t dH = hbA + slot * HTILE2;
#pragma unroll
    for (int it = 0; it < 8; it++) {
        int idx = it * 128 + ltid;        // 1024 granules, 128 threads
        int row = idx >> 4, seg = idx & 15;
        cpasync16(dH + row * HROW2 + seg * 16, hhi + (size_t)row * HH + k0 + seg * 8);
    }
    cpcommit();
}

__global__ __launch_bounds__(256, 1)
void lstm_persist(const float* __restrict__ pre, const float* __restrict__ Whh,
                  __nv_bfloat16* __restrict__ hb,
                  float* __restrict__ y,
                  __nv_bfloat16* __restrict__ yh, __nv_bfloat16* __restrict__ yl,
                  const float* __restrict__ res)
{
    extern __shared__ __align__(128) char rsm[];
    char* Whi = rsm;
    char* Wlo = rsm + WTILE;
    char* Hb  = rsm + 2 * WTILE;                        // 4 slots, hi only
    float* Csm0 = (float*)(rsm + 2 * WTILE + 4 * HTILE2);
    float* Csm1 = Csm0 + 64 * 28;

    int tid = threadIdx.x;
    int lane = tid & 31;
    int wid = tid >> 5;
    int gid = wid >> 2;          // warp group 0/1
    int w = wid & 3;             // row group within warp group
    int ltid = tid & 127;
    int j0 = blockIdx.x * JC;
    unsigned e0 = 0;
    if (tid == 0) e0 = *(volatile unsigned*)&g_epoch;

    float* CsmMy = gid ? Csm1 : Csm0;

    // cache Whh slice as bf16 hi/lo. SMEM row r = gate r/JC, col j0 + r%JC.
    for (int i = tid; i < NC * HH; i += 256) {
        int r = i / HH, k = i - r * HH;
        int g = r / JC, jj = r - g * JC;
        float v = Whh[(size_t)(g * HH + j0 + jj) * HH + k];
        __nv_bfloat16 h = __float2bfloat16(v);
        ((__nv_bfloat16*)(Whi + r * WROWB))[k] = h;
        ((__nv_bfloat16*)(Wlo + r * WROWB))[k] = __float2bfloat16(v - __bfloat162float(h));
    }

    // zero h (parity 0) for owned columns
    if (tid < BB) {
        __nv_bfloat16 z = __float2bfloat16(0.f);
#pragma unroll
        for (int jj = 0; jj < JC; jj++)
            hb[tid * HH + j0 + jj] = z;
    }
    grid_barrier(e0, 1);

    uint32_t hbA = smem_u32(Hb);
    uint32_t wA[2] = { smem_u32(Whi), smem_u32(Wlo) };

    // ldmatrix address components (proven layout)
    int aRow = (lane & 15);
    int aHalf = (lane >> 4) * 16;
    int gB = lane >> 3;
    int fi01 = (gB >> 1) * 8 + (lane & 7);
    int bHalf01 = (gB & 1) * 16;
    int row2 = 16 + (lane & 7);
    int bHalf2 = ((lane >> 3) & 1) * 16;
    int g4 = lane >> 2, tig = lane & 3;

    // cell-update partition
    int b0c = tid / JC, j0c = tid - b0c * JC;
    int b1c = (256 + tid) / JC, j1c = (256 + tid) - b1c * JC;
    bool has2 = (tid < 128);
    float cr0 = 0.f, cr1 = 0.f;

    for (int t = 0; t < TT; t++) {
        int pin = t & 1;
        const __nv_bfloat16* hin = hb + (size_t)pin * BBHH;
        __nv_bfloat16* hout = hb + (size_t)(pin ^ 1) * BBHH;

        // group preamble: issue chunks gid*3, gid*3+1 into slots gid*2, gid*2+1
        rec_issue(hbA, gid * 2 + 0, hin, (gid * 3 + 0) * KCH, ltid);
        rec_issue(hbA, gid * 2 + 1, hin, (gid * 3 + 1) * KCH, ltid);

        // preload pre[t] / res[t] into registers
        float pr0[4], pr1[4], rv0 = 0.f, rv1 = 0.f;
        {
            int jj = j0 + j0c;
            size_t prow = ((size_t)b0c * TT + t) * GG;
            pr0[0] = pre[prow + 0*HH + jj];
            pr0[1] = pre[prow + 1*HH + jj];
            pr0[2] = pre[prow + 2*HH + jj];
            pr0[3] = pre[prow + 3*HH + jj];
            if (res) rv0 = res[((size_t)b0c * TT + t) * HH + jj];
        }
        if (has2) {
            int jj = j0 + j1c;
            size_t prow = ((size_t)b1c * TT + t) * GG;
            pr1[0] = pre[prow + 0*HH + jj];
            pr1[1] = pre[prow + 1*HH + jj];
            pr1[2] = pre[prow + 2*HH + jj];
            pr1[3] = pre[prow + 3*HH + jj];
            if (res) rv1 = res[((size_t)b1c * TT + t) * HH + jj];
        }

        float acc[3][4];
#pragma unroll
        for (int f = 0; f < 3; f++)
#pragma unroll
            for (int r = 0; r < 4; r++) acc[f][r] = 0.f;

        // group-local chunk loop: 3 chunks, 2-slot ring; gates = h @ (Whi + Wlo)
#pragma unroll
        for (int i = 0; i < 3; i++) {
            int c = gid * 3 + i;
            int slot = gid * 2 + (i & 1);
            if (i == 2) cpwait<0>(); else cpwait<1>();
            barsync(1 + gid);
            uint32_t Abase = hbA + slot * HTILE2;
            uint32_t Whc = wA[0] + c * 256;
            uint32_t Wlc = wA[1] + c * 256;
#pragma unroll
            for (int kk = 0; kk < 8; kk++) {
                uint32_t a[4];
                ldsm4(Abase + (w*16 + aRow) * HROW2 + aHalf + kk*32, a);
                uint32_t bh01[4], bh2[2], bl01[4], bl2[2];
                ldsm4(Whc + fi01 * WROWB + bHalf01 + kk*32, bh01);
                ldsm2(Whc + row2 * WROWB + bHalf2 + kk*32, bh2);
                ldsm4(Wlc + fi01 * WROWB + bHalf01 + kk*32, bl01);
                ldsm2(Wlc + row2 * WROWB + bHalf2 + kk*32, bl2);
                mma_bf16(acc[0], a, bh01[0], bh01[1]);
                mma_bf16(acc[1], a, bh01[2], bh01[3]);
                mma_bf16(acc[2], a, bh2[0], bh2[1]);
                mma_bf16(acc[0], a, bl01[0], bl01[1]);
                mma_bf16(acc[1], a, bl01[2], bl01[3]);
                mma_bf16(acc[2], a, bl2[0], bl2[1]);
            }
            barsync(1 + gid);
            if (i == 0)
                rec_issue(hbA, slot, hin, (gid * 3 + 2) * KCH, ltid);
        }

        // write partial gate tile to this group's Csm region
#pragma unroll
        for (int f = 0; f < 3; f++) {
            CsmMy[(w*16 + g4) * 28 + f*8 + tig*2]     = acc[f][0];
            CsmMy[(w*16 + g4) * 28 + f*8 + tig*2 + 1] = acc[f][1];
            CsmMy[(w*16 + 8 + g4) * 28 + f*8 + tig*2]     = acc[f][2];
            CsmMy[(w*16 + 8 + g4) * 28 + f*8 + tig*2 + 1] = acc[f][3];
        }
        __syncthreads();

        // cell update (c in registers); y written fp32 + bf16 hi/lo split
        {
            int b = b0c, jj = j0c, j = j0 + jj;
            float gi = Csm0[b*28 + 0*JC + jj] + Csm1[b*28 + 0*JC + jj] + pr0[0];
            float gf = Csm0[b*28 + 1*JC + jj] + Csm1[b*28 + 1*JC + jj] + pr0[1];
            float gg = Csm0[b*28 + 2*JC + jj] + Csm1[b*28 + 2*JC + jj] + pr0[2];
            float go = Csm0[b*28 + 3*JC + jj] + Csm1[b*28 + 3*JC + jj] + pr0[3];
            float si = fsigmoid(gi), sf_ = fsigmoid(gf), so = fsigmoid(go);
            float tg = ftanh(gg);
            float cn = sf_ * cr0 + si * tg;
            float hn = so * ftanh(cn);
            cr0 = cn;
            hout[b * HH + j] = __float2bfloat16(hn);
            float yv = res ? hn + rv0 : hn;
            size_t yi = ((size_t)b * TT + t) * HH + j;
            y[yi] = yv;
            __nv_bfloat16 vh = __float2bfloat16(yv);
            yh[yi] = vh;
            yl[yi] = __float2bfloat16(yv - __bfloat162float(vh));
        }
        if (has2) {
            int b = b1c, jj = j1c, j = j0 + jj;
            float gi = Csm0[b*28 + 0*JC + jj] + Csm1[b*28 + 0*JC + jj] + pr1[0];
            float gf = Csm0[b*28 + 1*JC + jj] + Csm1[b*28 + 1*JC + jj] + pr1[1];
            float gg = Csm0[b*28 + 2*JC + jj] + Csm1[b*28 + 2*JC + jj] + pr1[2];
            float go = Csm0[b*28 + 3*JC + jj] + Csm1[b*28 + 3*JC + jj] + pr1[3];
            float si = fsigmoid(gi), sf_ = fsigmoid(gf), so = fsigmoid(go);
            float tg = ftanh(gg);
            float cn = sf_ * cr1 + si * tg;
            float hn = so * ftanh(cn);
            cr1 = cn;
            hout[b * HH + j] = __float2bfloat16(hn);
            float yv = res ? hn + rv1 : hn;
            size_t yi = ((size_t)b * TT + t) * HH + j;
            y[yi] = yv;
            __nv_bfloat16 vh = __float2bfloat16(yv);
            yh[yi] = vh;
            yl[yi] = __float2bfloat16(yv - __bfloat162float(vh));
        }
        grid_barrier(e0, t + 2);
    }
}

// ---------------- output copy ----------------
__global__ void copy_out(float* __restrict__ out, const float* __restrict__ proj, int n)
{
    int i = blockIdx.x * blockDim.x + threadIdx.x;
    int stride = gridDim.x * blockDim.x;
    for (; i < n; i += stride) {
        int m = i / OUTD, o = i % OUTD;
        out[i] = proj[(size_t)m * 128 + o];
    }
}

// ---------------- driver ----------------
extern "C" void kernel_launch(void* const* d_in, const int* in_sizes, int n_in,
                              void* d_out, int out_size)
{
    const float* x   = (const float*)d_in[0];
    const float* Wih[3] = { (const float*)d_in[1], (const float*)d_in[4], (const float*)d_in[7] };
    const float* Whh[3] = { (const float*)d_in[2], (const float*)d_in[5], (const float*)d_in[8] };
    const float* bgt[3] = { (const float*)d_in[3], (const float*)d_in[6], (const float*)d_in[9] };
    const float* Wp  = (const float*)d_in[10];

    float *pre, *x1, *x2, *x3, *proj;
    __nv_bfloat16 *ah, *al, *bh, *bl, *pph, *ppl, *hbp;
    cudaGetSymbolAddress((void**)&pre,  g_pre);
    cudaGetSymbolAddress((void**)&x1,   g_x1);
    cudaGetSymbolAddress((void**)&x2,   g_x2);
    cudaGetSymbolAddress((void**)&x3,   g_x3);
    cudaGetSymbolAddress((void**)&proj, g_proj);
    cudaGetSymbolAddress((void**)&hbp,  g_hb);
    cudaGetSymbolAddress((void**)&ah,   g_ah);
    cudaGetSymbolAddress((void**)&al,   g_al);
    cudaGetSymbolAddress((void**)&bh,   g_bh);
    cudaGetSymbolAddress((void**)&bl,   g_bl);
    cudaGetSymbolAddress((void**)&pph,  g_ph);
    cudaGetSymbolAddress((void**)&ppl,  g_pl);

    cudaFuncSetAttribute(lstm_persist, cudaFuncAttributeMaxDynamicSharedMemorySize, RSMEM);
    cudaFuncSetAttribute(gemm_mma3, cudaFuncAttributeMaxDynamicSharedMemorySize, GSMEM);

    float* xs[3] = { x1, x2, x3 };
    const float* layerIn = x;
    int K = INF;

    for (int L = 0; L < 3; L++) {
        // activation split: only needed for the raw input; layers 1-3 get
        // their hi/lo split written directly by the previous lstm_persist.
        if (L == 0)
            split_bf16<<<4096, 256>>>(layerIn, ah, al, (size_t)MM * K / 4);
        split_bf16<<<512, 256>>>(Wih[L], bh, bl, (size_t)GG * K / 4);

        dim3 grid(GG / 128, MM / 128);
        gemm_mma3<<<grid, 256, GSMEM>>>(ah, al, bh, bl, bgt[L], pre, K, GG);

        const float* res = (L > 0) ? layerIn : nullptr;
        lstm_persist<<<NCTA, 256, RSMEM>>>(pre, Whh[L], hbp, xs[L], ah, al, res);

        layerIn = xs[L];
        K = HH;
    }

    // projection: ah/al already hold x3's split (written by layer-3 lstm)
    pad_wp_split<<<96, 256>>>(pph, ppl, Wp);
    dim3 gridP(1, MM / 128);
    gemm_mma3<<<gridP, 256, GSMEM>>>(ah, al, pph, ppl, nullptr, proj, HH, 128);
    copy_out<<<1024, 256>>>((float*)d_out, proj, MM * OUTD);
}